// round 9
// baseline (speedup 1.0000x reference)
#include <cuda_runtime.h>
#include <cuda_fp16.h>
#include <math.h>
#include <stdint.h>

// Problem constants
#define Bv 8
#define Tv 1024
#define Cv 1024
#define Hv 16
#define DHv 64
#define Fv 4096
#define BT (Bv*Tv)          // 8192
#define QKVN (3*Cv)         // 3072

// ---------------- scratch ----------------
__device__ __half g_x1h[BT*Cv];         // ln1(x) fp16 (GEMM A + residual)
__device__ __half g_qkvh[BT*QKVN];      // qkv fp16
__device__ __half g_Wqkvh[QKVN*Cv];     // packed weight [N=3C, K=C] fp16
__device__ float  g_bqkv[QKVN];
__device__ float  g_Mpart[4*128*DHv*DHv]; // partial (K^T V)/32
__device__ __half g_Wt[Bv*Cv*Cv];       // per-batch fused proj weight [b][n][k] fp16
__device__ float  g_y[BT*Cv];           // x1 + attn fp32
__device__ __half g_x2h[BT*Cv];         // ln2(y) fp16 (GEMM A + residual)
__device__ __half g_hh[BT*Fv];          // gelu(...) fp16
__device__ __half g_W1Th[Fv*Cv];        // [N=F, K=C] fp16
__device__ __half g_W2Th[Cv*Fv];        // [N=C, K=F] fp16

// ---------------- helpers ----------------
__device__ __forceinline__ uint32_t smem_u32(const void* p) {
    uint32_t a;
    asm("{ .reg .u64 t; cvta.to.shared.u64 t, %1; cvt.u32.u64 %0, t; }" : "=r"(a) : "l"(p));
    return a;
}
__device__ __forceinline__ void cp_async16(uint32_t dst, const void* src) {
    asm volatile("cp.async.cg.shared.global [%0], [%1], 16;" :: "r"(dst), "l"(src) : "memory");
}
__device__ __forceinline__ void cp_commit() { asm volatile("cp.async.commit_group;" ::: "memory"); }
template<int N> __device__ __forceinline__ void cp_wait() {
    asm volatile("cp.async.wait_group %0;" :: "n"(N) : "memory");
}

__device__ __forceinline__ void mma_f16(float* d, const uint32_t* a, const uint32_t* b) {
    asm volatile(
        "mma.sync.aligned.m16n8k16.row.col.f32.f16.f16.f32 "
        "{%0,%1,%2,%3}, {%4,%5,%6,%7}, {%8,%9}, {%0,%1,%2,%3};"
        : "+f"(d[0]), "+f"(d[1]), "+f"(d[2]), "+f"(d[3])
        : "r"(a[0]), "r"(a[1]), "r"(a[2]), "r"(a[3]), "r"(b[0]), "r"(b[1]));
}

__device__ __forceinline__ float gelu_f(float v) {
    return 0.5f * v * (1.0f + erff(v * 0.70710678118654752f));
}

// ---------------- fp16 mma.sync GEMM ----------------
// C[M,N] = A[M,K](row stride lda) * B^T (B given [N,K]) (+ per-batch B if BATB)
// 128x128 CTA tile, 256 threads (8 warps 4x2), warp tile 32x64, BK=64, 2-stage cp.async.
// EPI: 0 = +bias ; 1 = +bias + fp16 res ; 2 = gelu(+bias). HOUT: 0 fp32 C, 1 fp16 C.
// BATB: B += (m0>>10)*N*K  (per-1024-row batch weights)
#define NSTAGE 2
#define ROWH   72
#define TILEH  (128*ROWH)
#define TILEB  (TILEH*2)               // 18432 bytes
#define STAGEB (2*TILEB)               // 36864 bytes

template<int EPI, int HOUT, int BATB>
__global__ __launch_bounds__(256, 2)
void mm_gemm(const __half* __restrict__ A, int lda, const __half* __restrict__ B,
             const float* __restrict__ bias, const __half* __restrict__ res,
             void* __restrict__ Cout, int M, int N, int K)
{
    extern __shared__ __half sm[];
    const int tid = threadIdx.x, wid = tid >> 5, lane = tid & 31;
    const int m0 = blockIdx.y * 128, n0 = blockIdx.x * 128;
    const int wm = wid & 3, wn = wid >> 2;
    const uint32_t sbase = smem_u32(sm);
    const __half* Bb = BATB ? (B + (size_t)(m0 >> 10) * N * K) : B;

    const __half* aSrc[4]; uint32_t adst[4];
    const __half* bSrc[4]; uint32_t bdst[4];
    #pragma unroll
    for (int u = 0; u < 4; u++) {
        int idx = u * 256 + tid;
        int row = idx >> 3, c = idx & 7;
        aSrc[u] = A + (size_t)(m0 + row) * lda + c * 8;
        bSrc[u] = Bb + (size_t)(n0 + row) * K + c * 8;
        adst[u] = row * (ROWH * 2) + c * 16;
        bdst[u] = TILEB + adst[u];
    }

    #define ISSUE_STAGE(st, it) do {                                          \
        uint32_t _sb = sbase + (st) * STAGEB;                                 \
        _Pragma("unroll") for (int _u = 0; _u < 4; _u++)                      \
            cp_async16(_sb + adst[_u], aSrc[_u] + (size_t)(it) * 64);         \
        _Pragma("unroll") for (int _u = 0; _u < 4; _u++)                      \
            cp_async16(_sb + bdst[_u], bSrc[_u] + (size_t)(it) * 64);         \
        cp_commit(); } while (0)

    int aoff[2], boff[8];
    #pragma unroll
    for (int mi = 0; mi < 2; mi++)
        aoff[mi] = (wm * 32 + mi * 16 + (lane >> 2)) * ROWH + (lane & 3) * 2;
    #pragma unroll
    for (int nj = 0; nj < 8; nj++)
        boff[nj] = (wn * 64 + nj * 8 + (lane >> 2)) * ROWH + (lane & 3) * 2;

    float acc[2][8][4];
    #pragma unroll
    for (int mi = 0; mi < 2; mi++)
        #pragma unroll
        for (int nj = 0; nj < 8; nj++)
            #pragma unroll
            for (int q = 0; q < 4; q++) acc[mi][nj][q] = 0.f;

    const int NIT = K >> 6;
    ISSUE_STAGE(0, 0);

    for (int it = 0; it < NIT; it++) {
        cp_wait<0>();
        __syncthreads();
        if (it + 1 < NIT) ISSUE_STAGE((it + 1) & 1, it + 1);

        const __half* sA = sm + (it & 1) * (STAGEB / 2);
        const __half* sB = sA + TILEH;
        #pragma unroll
        for (int kk = 0; kk < 4; kk++) {
            uint32_t af[2][4], bf[8][2];
            #pragma unroll
            for (int mi = 0; mi < 2; mi++) {
                int o = aoff[mi] + kk * 16;
                af[mi][0] = *(const uint32_t*)(sA + o);
                af[mi][1] = *(const uint32_t*)(sA + o + 8 * ROWH);
                af[mi][2] = *(const uint32_t*)(sA + o + 8);
                af[mi][3] = *(const uint32_t*)(sA + o + 8 * ROWH + 8);
            }
            #pragma unroll
            for (int nj = 0; nj < 8; nj++) {
                int o = boff[nj] + kk * 16;
                bf[nj][0] = *(const uint32_t*)(sB + o);
                bf[nj][1] = *(const uint32_t*)(sB + o + 8);
            }
            #pragma unroll
            for (int mi = 0; mi < 2; mi++)
                #pragma unroll
                for (int nj = 0; nj < 8; nj++)
                    mma_f16(acc[mi][nj], af[mi], bf[nj]);
        }
    }

    #pragma unroll
    for (int mi = 0; mi < 2; mi++) {
        int r0 = m0 + wm * 32 + mi * 16 + (lane >> 2);
        #pragma unroll
        for (int nj = 0; nj < 8; nj++) {
            int cb = n0 + wn * 64 + nj * 8 + (lane & 3) * 2;
            float2 bv = *(const float2*)(bias + cb);
            #pragma unroll
            for (int half_ = 0; half_ < 2; half_++) {
                int r = r0 + half_ * 8;
                float vx = acc[mi][nj][half_ * 2 + 0] + bv.x;
                float vy = acc[mi][nj][half_ * 2 + 1] + bv.y;
                if (EPI == 1) {
                    __half2 rv = *(const __half2*)(res + (size_t)r * N + cb);
                    float2 rf = __half22float2(rv);
                    vx += rf.x; vy += rf.y;
                }
                if (EPI == 2) { vx = gelu_f(vx); vy = gelu_f(vy); }
                if (HOUT) {
                    *(__half2*)((__half*)Cout + (size_t)r * N + cb) = __floats2half2_rn(vx, vy);
                } else {
                    *(float2*)((float*)Cout + (size_t)r * N + cb) = make_float2(vx, vy);
                }
            }
        }
    }
    #undef ISSUE_STAGE
}

// ---------------- LayerNorm -> fp16 ----------------
__global__ void ln_kernel(const float* __restrict__ x, const float* __restrict__ w,
                          const float* __restrict__ bb, __half* __restrict__ yh)
{
    int row = blockIdx.x;
    int t = threadIdx.x;
    const float4* xr = (const float4*)(x + (size_t)row * Cv);
    float4 v = xr[t];
    float s  = v.x + v.y + v.z + v.w;
    float ss = v.x*v.x + v.y*v.y + v.z*v.z + v.w*v.w;
    #pragma unroll
    for (int o = 16; o > 0; o >>= 1) {
        s  += __shfl_xor_sync(0xffffffffu, s,  o);
        ss += __shfl_xor_sync(0xffffffffu, ss, o);
    }
    __shared__ float shs[8], shss[8], par[2];
    if ((t & 31) == 0) { shs[t >> 5] = s; shss[t >> 5] = ss; }
    __syncthreads();
    if (t == 0) {
        float S = 0.f, SS = 0.f;
        #pragma unroll
        for (int i = 0; i < 8; i++) { S += shs[i]; SS += shss[i]; }
        float mu  = S * (1.0f / 1024.0f);
        float var = SS * (1.0f / 1024.0f) - mu * mu;
        par[0] = mu; par[1] = rsqrtf(var + 1e-3f);
    }
    __syncthreads();
    float mu = par[0], rs = par[1];
    float4 wv = ((const float4*)w)[t];
    float4 bv = ((const float4*)bb)[t];
    float ox = (v.x - mu) * rs * wv.x + bv.x;
    float oy = (v.y - mu) * rs * wv.y + bv.y;
    float oz = (v.z - mu) * rs * wv.z + bv.z;
    float ow = (v.w - mu) * rs * wv.w + bv.w;
    __half2* yh2 = (__half2*)(yh + (size_t)row * Cv);
    yh2[2 * t + 0] = __floats2half2_rn(ox, oy);
    yh2[2 * t + 1] = __floats2half2_rn(oz, ow);
}

// ---------------- fused weight prep: pack QKV + transpose W1/W2 ----------------
// grid ranges: [0,3072) pack; [3072,7168) W1T (128x32); [7168,11264) W2T (32x128)
#define PACK_BLKS 3072
#define W1T_BLKS  4096
#define W2T_BLKS  4096
__global__ void prep_kernel(const float* __restrict__ Wq, const float* __restrict__ Wk,
                            const float* __restrict__ Wv,
                            const float* __restrict__ bq, const float* __restrict__ bk,
                            const float* __restrict__ bv,
                            const float* __restrict__ W1, const float* __restrict__ W2,
                            __half* __restrict__ Wqkvh, float* __restrict__ bqkv,
                            __half* __restrict__ W1Th, __half* __restrict__ W2Th)
{
    __shared__ float tile[32][33];
    int blk = blockIdx.x, tid = threadIdx.x;
    if (blk < PACK_BLKS) {
        int gid = blk * 256 + tid;                 // 786432 threads
        #pragma unroll
        for (int u = 0; u < 4; u++) {
            int idx = u * (PACK_BLKS * 256) + gid; // over 3C*C
            int n = idx / Cv, k = idx % Cv;
            int sel = n >> 10;
            int hh = (n & 1023) >> 6, d = n & 63;
            const float* W = (sel == 0) ? Wq : (sel == 1) ? Wk : Wv;
            Wqkvh[idx] = __float2half(W[((size_t)hh * Cv + k) * DHv + d]);
            if (k == 0) {
                const float* B = (sel == 0) ? bq : (sel == 1) ? bk : bv;
                bqkv[n] = B[hh * DHv + d];
            }
        }
        return;
    }
    // transpose branch
    const float* in; __half* outp; int R, Cc, bx, by;
    if (blk < PACK_BLKS + W1T_BLKS) {
        int b2 = blk - PACK_BLKS;                  // grid (Fv/32=128, Cv/32=32)
        in = W1; outp = W1Th; R = Cv; Cc = Fv;
        bx = (b2 & 127) * 32; by = (b2 >> 7) * 32;
    } else {
        int b2 = blk - PACK_BLKS - W1T_BLKS;       // grid (Cv/32=32, Fv/32=128)
        in = W2; outp = W2Th; R = Fv; Cc = Cv;
        bx = (b2 & 31) * 32; by = (b2 >> 5) * 32;
    }
    int tx = tid & 31, ty = tid >> 5;              // 32x8
    #pragma unroll
    for (int j = 0; j < 32; j += 8)
        tile[ty + j][tx] = in[(size_t)(by + ty + j) * Cc + bx + tx];
    __syncthreads();
    #pragma unroll
    for (int j = 0; j < 32; j += 8)
        outp[(size_t)(bx + ty + j) * R + by + tx] = __float2half(tile[tx][ty + j]);
}

// --------- attention collapsed: Mpart[p] = (K[p]^T V[p]) * C^-0.5, fp16 inputs ---------
__global__ void ktv_kernel(const __half* __restrict__ qkv, float* __restrict__ Mp)
{
    int bh = blockIdx.x;               // 128
    int part = blockIdx.y;             // 4
    int b = bh >> 4, h = bh & 15;
    __shared__ float Ks[32][64], Vs[32][64];
    int tid = threadIdx.x;
    int ty = tid >> 4, tx = tid & 15;
    float acc[4][4];
    #pragma unroll
    for (int i = 0; i < 4; i++)
        #pragma unroll
        for (int j = 0; j < 4; j++) acc[i][j] = 0.f;

    const __half* baseK = qkv + (size_t)b * Tv * QKVN + 1024 + h * 64;
    const __half* baseV = baseK + 1024;
    int tlo = part * 256, thi = tlo + 256;

    for (int t0 = tlo; t0 < thi; t0 += 32) {
        #pragma unroll
        for (int u = 0; u < 4; u++) {
            int idx = tid + 256 * u;
            int r = idx >> 5, c2 = idx & 31;
            __half2 kv = *(const __half2*)(baseK + (size_t)(t0 + r) * QKVN + c2 * 2);
            __half2 vv = *(const __half2*)(baseV + (size_t)(t0 + r) * QKVN + c2 * 2);
            float2 kf = __half22float2(kv), vf = __half22float2(vv);
            Ks[r][c2 * 2] = kf.x; Ks[r][c2 * 2 + 1] = kf.y;
            Vs[r][c2 * 2] = vf.x; Vs[r][c2 * 2 + 1] = vf.y;
        }
        __syncthreads();
        #pragma unroll
        for (int tt = 0; tt < 32; tt++) {
            float a[4], v[4];
            #pragma unroll
            for (int i = 0; i < 4; i++) a[i] = Ks[tt][ty * 4 + i];
            #pragma unroll
            for (int j = 0; j < 4; j++) v[j] = Vs[tt][tx * 4 + j];
            #pragma unroll
            for (int i = 0; i < 4; i++)
                #pragma unroll
                for (int j = 0; j < 4; j++)
                    acc[i][j] += a[i] * v[j];
        }
        __syncthreads();
    }
    float* out = Mp + ((size_t)part * 128 + bh) * 4096;
    #pragma unroll
    for (int i = 0; i < 4; i++)
        #pragma unroll
        for (int j = 0; j < 4; j++)
            out[(ty * 4 + i) * 64 + tx * 4 + j] = acc[i][j] * 0.03125f;
}

// --------- W~p fold: Wt[b][n][h*64+d] = sum_e M_bh[d][e] * Wp[h*64+e][n] ---------
__global__ void wtilde_kernel(const float* __restrict__ Mp, const float* __restrict__ Wp,
                              __half* __restrict__ Wt)
{
    int bh = blockIdx.x;               // 128
    int b = bh >> 4, h = bh & 15;
    __shared__ float Ms[64][65];
    __shared__ float Ws[64][65];
    int tid = threadIdx.x;

    // sum 4 M parts
    const float* p0 = Mp + ((size_t)0 * 128 + bh) * 4096;
    const float* p1 = Mp + ((size_t)1 * 128 + bh) * 4096;
    const float* p2 = Mp + ((size_t)2 * 128 + bh) * 4096;
    const float* p3 = Mp + ((size_t)3 * 128 + bh) * 4096;
    #pragma unroll
    for (int u = 0; u < 16; u++) {
        int i = tid + 256 * u;         // 0..4095
        int d = i >> 6, e = i & 63;
        Ms[d][e] = p0[i] + p1[i] + p2[i] + p3[i];
    }
    __syncthreads();

    int d = tid & 63, ng = tid >> 6;   // d fixed per thread, 4 n-groups
    for (int n0 = 0; n0 < Cv; n0 += 64) {
        // load Wp rows h*64..h*64+63, cols n0..n0+63
        #pragma unroll
        for (int u = 0; u < 16; u++) {
            int i = tid + 256 * u;     // 0..4095
            int e = i >> 6, nl = i & 63;
            Ws[e][nl] = Wp[(size_t)(h * 64 + e) * Cv + n0 + nl];
        }
        __syncthreads();
        float acc[16];
        #pragma unroll
        for (int v = 0; v < 16; v++) acc[v] = 0.f;
        #pragma unroll
        for (int e = 0; e < 64; e++) {
            float m = Ms[d][e];
            #pragma unroll
            for (int v = 0; v < 16; v++)
                acc[v] += m * Ws[e][ng * 16 + v];
        }
        __half* outb = Wt + (size_t)b * Cv * Cv + (size_t)(n0 + ng * 16) * Cv + h * 64 + d;
        #pragma unroll
        for (int v = 0; v < 16; v++)
            outb[(size_t)v * Cv] = __float2half(acc[v]);
        __syncthreads();
    }
}

// ---------------- launch ----------------
extern "C" void kernel_launch(void* const* d_in, const int* in_sizes, int n_in,
                              void* d_out, int out_size)
{
    (void)in_sizes; (void)n_in; (void)out_size;
    const float* x    = (const float*)d_in[0];
    const float* Wq   = (const float*)d_in[1];
    const float* bq   = (const float*)d_in[2];
    const float* Wk   = (const float*)d_in[3];
    const float* bk   = (const float*)d_in[4];
    const float* Wv   = (const float*)d_in[5];
    const float* bv   = (const float*)d_in[6];
    const float* Wp   = (const float*)d_in[7];
    const float* bp   = (const float*)d_in[8];
    const float* W1   = (const float*)d_in[9];
    const float* b1   = (const float*)d_in[10];
    const float* W2   = (const float*)d_in[11];
    const float* b2   = (const float*)d_in[12];
    const float* ln1w = (const float*)d_in[13];
    const float* ln1b = (const float*)d_in[14];
    const float* ln2w = (const float*)d_in[15];
    const float* ln2b = (const float*)d_in[16];
    float* out = (float*)d_out;

    float *pbqkv, *pMp, *py;
    __half *px1h, *pqkvh, *pWqkvh, *pWt, *px2h, *phh, *pW1Th, *pW2Th;
    cudaGetSymbolAddress((void**)&px1h,   g_x1h);
    cudaGetSymbolAddress((void**)&pqkvh,  g_qkvh);
    cudaGetSymbolAddress((void**)&pWqkvh, g_Wqkvh);
    cudaGetSymbolAddress((void**)&pbqkv,  g_bqkv);
    cudaGetSymbolAddress((void**)&pMp,    g_Mpart);
    cudaGetSymbolAddress((void**)&pWt,    g_Wt);
    cudaGetSymbolAddress((void**)&py,     g_y);
    cudaGetSymbolAddress((void**)&px2h,   g_x2h);
    cudaGetSymbolAddress((void**)&phh,    g_hh);
    cudaGetSymbolAddress((void**)&pW1Th,  g_W1Th);
    cudaGetSymbolAddress((void**)&pW2Th,  g_W2Th);

    const int smem = NSTAGE * STAGEB;   // 73728
    cudaFuncSetAttribute(mm_gemm<0,1,0>, cudaFuncAttributeMaxDynamicSharedMemorySize, smem);
    cudaFuncSetAttribute(mm_gemm<1,0,1>, cudaFuncAttributeMaxDynamicSharedMemorySize, smem);
    cudaFuncSetAttribute(mm_gemm<1,0,0>, cudaFuncAttributeMaxDynamicSharedMemorySize, smem);
    cudaFuncSetAttribute(mm_gemm<2,1,0>, cudaFuncAttributeMaxDynamicSharedMemorySize, smem);

    // fused weight prep (pack QKV + W1T + W2T), one launch
    prep_kernel<<<PACK_BLKS + W1T_BLKS + W2T_BLKS, 256>>>(
        Wq, Wk, Wv, bq, bk, bv, W1, W2, pWqkvh, pbqkv, pW1Th, pW2Th);

    // x1 = LN1(x) -> fp16
    ln_kernel<<<BT, 256>>>(x, ln1w, ln1b, px1h);
    // qkv = x1 @ Wqkv^T + b -> fp16
    mm_gemm<0,1,0><<<dim3(QKVN/128, BT/128), 256, smem>>>(px1h, Cv, pWqkvh, pbqkv, nullptr, pqkvh, BT, QKVN, Cv);
    // M = (K^T V)/32 (4-way T split)
    ktv_kernel<<<dim3(Bv * Hv, 4), 256>>>(pqkvh, pMp);
    // fold M into proj weights: Wt_b = blockdiag(M) @ Wp
    wtilde_kernel<<<Bv * Hv, 256>>>(pMp, Wp, pWt);
    // y = x1 + Q @ Wt_b + bp   (A = Q section of qkv, lda=3C; B batched)
    mm_gemm<1,0,1><<<dim3(Cv/128, BT/128), 256, smem>>>(pqkvh, QKVN, pWt, bp, px1h, py, BT, Cv, Cv);
    // x2 = LN2(y) -> fp16
    ln_kernel<<<BT, 256>>>(py, ln2w, ln2b, px2h);
    // h = gelu(x2 @ W1 + b1) -> fp16
    mm_gemm<2,1,0><<<dim3(Fv/128, BT/128), 256, smem>>>(px2h, Cv, pW1Th, b1, nullptr, phh, BT, Fv, Cv);
    // out = x2 + h @ W2 + b2 -> fp32
    mm_gemm<1,0,0><<<dim3(Cv/128, BT/128), 256, smem>>>(phh, Fv, pW2Th, b2, px2h, out, BT, Cv, Fv);
}

// round 10
// speedup vs baseline: 1.0229x; 1.0229x over previous
#include <cuda_runtime.h>
#include <cuda_fp16.h>
#include <math.h>
#include <stdint.h>

// Problem constants
#define Bv 8
#define Tv 1024
#define Cv 1024
#define Hv 16
#define DHv 64
#define Fv 4096
#define BT (Bv*Tv)          // 8192
#define QKVN (3*Cv)         // 3072
#define NPART 8

// ---------------- scratch ----------------
__device__ __half g_x1h[BT*Cv];         // ln1(x) fp16 (GEMM A + residual)
__device__ __half g_qkvh[BT*QKVN];      // qkv fp16
__device__ __half g_Wqkvh[QKVN*Cv];     // packed weight [N=3C, K=C] fp16
__device__ float  g_bqkv[QKVN];
__device__ float  g_Mpart[NPART*128*DHv*DHv]; // partial (K^T V)/32
__device__ float  g_M[128*DHv*DHv];     // reduced M per (b,h)
__device__ __half g_Wt[Bv*Cv*Cv];       // per-batch fused proj weight [b][n][k] fp16
__device__ __half g_yh[BT*Cv];          // x1 + attn fp16
__device__ __half g_x2h[BT*Cv];         // ln2(y) fp16 (GEMM A + residual)
__device__ __half g_hh[BT*Fv];          // gelu(...) fp16
__device__ __half g_W1Th[Fv*Cv];        // [N=F, K=C] fp16
__device__ __half g_W2Th[Cv*Fv];        // [N=C, K=F] fp16

// ---------------- helpers ----------------
__device__ __forceinline__ uint32_t smem_u32(const void* p) {
    uint32_t a;
    asm("{ .reg .u64 t; cvta.to.shared.u64 t, %1; cvt.u32.u64 %0, t; }" : "=r"(a) : "l"(p));
    return a;
}
__device__ __forceinline__ void cp_async16(uint32_t dst, const void* src) {
    asm volatile("cp.async.cg.shared.global [%0], [%1], 16;" :: "r"(dst), "l"(src) : "memory");
}
__device__ __forceinline__ void cp_commit() { asm volatile("cp.async.commit_group;" ::: "memory"); }
template<int N> __device__ __forceinline__ void cp_wait() {
    asm volatile("cp.async.wait_group %0;" :: "n"(N) : "memory");
}

__device__ __forceinline__ void mma_f16(float* d, const uint32_t* a, const uint32_t* b) {
    asm volatile(
        "mma.sync.aligned.m16n8k16.row.col.f32.f16.f16.f32 "
        "{%0,%1,%2,%3}, {%4,%5,%6,%7}, {%8,%9}, {%0,%1,%2,%3};"
        : "+f"(d[0]), "+f"(d[1]), "+f"(d[2]), "+f"(d[3])
        : "r"(a[0]), "r"(a[1]), "r"(a[2]), "r"(a[3]), "r"(b[0]), "r"(b[1]));
}

__device__ __forceinline__ float gelu_f(float v) {
    return 0.5f * v * (1.0f + erff(v * 0.70710678118654752f));
}

// ---------------- fp16 mma.sync GEMM ----------------
// C[M,N] = A[M,K](row stride lda) * B^T (B given [N,K]) (+ per-batch B if BATB)
// 128x128 CTA tile, 256 threads (8 warps 4x2), warp tile 32x64, BK=64, 2-stage cp.async.
// EPI: 0 = +bias ; 1 = +bias + fp16 res ; 2 = gelu(+bias). HOUT: 0 fp32 C, 1 fp16 C.
#define NSTAGE 2
#define ROWH   72
#define TILEH  (128*ROWH)
#define TILEB  (TILEH*2)               // 18432 bytes
#define STAGEB (2*TILEB)               // 36864 bytes

template<int EPI, int HOUT, int BATB>
__global__ __launch_bounds__(256, 2)
void mm_gemm(const __half* __restrict__ A, int lda, const __half* __restrict__ B,
             const float* __restrict__ bias, const __half* __restrict__ res,
             void* __restrict__ Cout, int M, int N, int K)
{
    extern __shared__ __half sm[];
    const int tid = threadIdx.x, wid = tid >> 5, lane = tid & 31;
    const int m0 = blockIdx.y * 128, n0 = blockIdx.x * 128;
    const int wm = wid & 3, wn = wid >> 2;
    const uint32_t sbase = smem_u32(sm);
    const __half* Bb = BATB ? (B + (size_t)(m0 >> 10) * N * K) : B;

    const __half* aSrc[4]; uint32_t adst[4];
    const __half* bSrc[4]; uint32_t bdst[4];
    #pragma unroll
    for (int u = 0; u < 4; u++) {
        int idx = u * 256 + tid;
        int row = idx >> 3, c = idx & 7;
        aSrc[u] = A + (size_t)(m0 + row) * lda + c * 8;
        bSrc[u] = Bb + (size_t)(n0 + row) * K + c * 8;
        adst[u] = row * (ROWH * 2) + c * 16;
        bdst[u] = TILEB + adst[u];
    }

    #define ISSUE_STAGE(st, it) do {                                          \
        uint32_t _sb = sbase + (st) * STAGEB;                                 \
        _Pragma("unroll") for (int _u = 0; _u < 4; _u++)                      \
            cp_async16(_sb + adst[_u], aSrc[_u] + (size_t)(it) * 64);         \
        _Pragma("unroll") for (int _u = 0; _u < 4; _u++)                      \
            cp_async16(_sb + bdst[_u], bSrc[_u] + (size_t)(it) * 64);         \
        cp_commit(); } while (0)

    int aoff[2], boff[8];
    #pragma unroll
    for (int mi = 0; mi < 2; mi++)
        aoff[mi] = (wm * 32 + mi * 16 + (lane >> 2)) * ROWH + (lane & 3) * 2;
    #pragma unroll
    for (int nj = 0; nj < 8; nj++)
        boff[nj] = (wn * 64 + nj * 8 + (lane >> 2)) * ROWH + (lane & 3) * 2;

    float acc[2][8][4];
    #pragma unroll
    for (int mi = 0; mi < 2; mi++)
        #pragma unroll
        for (int nj = 0; nj < 8; nj++)
            #pragma unroll
            for (int q = 0; q < 4; q++) acc[mi][nj][q] = 0.f;

    const int NIT = K >> 6;
    ISSUE_STAGE(0, 0);

    for (int it = 0; it < NIT; it++) {
        cp_wait<0>();
        __syncthreads();
        if (it + 1 < NIT) ISSUE_STAGE((it + 1) & 1, it + 1);

        const __half* sA = sm + (it & 1) * (STAGEB / 2);
        const __half* sB = sA + TILEH;
        #pragma unroll
        for (int kk = 0; kk < 4; kk++) {
            uint32_t af[2][4], bf[8][2];
            #pragma unroll
            for (int mi = 0; mi < 2; mi++) {
                int o = aoff[mi] + kk * 16;
                af[mi][0] = *(const uint32_t*)(sA + o);
                af[mi][1] = *(const uint32_t*)(sA + o + 8 * ROWH);
                af[mi][2] = *(const uint32_t*)(sA + o + 8);
                af[mi][3] = *(const uint32_t*)(sA + o + 8 * ROWH + 8);
            }
            #pragma unroll
            for (int nj = 0; nj < 8; nj++) {
                int o = boff[nj] + kk * 16;
                bf[nj][0] = *(const uint32_t*)(sB + o);
                bf[nj][1] = *(const uint32_t*)(sB + o + 8);
            }
            #pragma unroll
            for (int mi = 0; mi < 2; mi++)
                #pragma unroll
                for (int nj = 0; nj < 8; nj++)
                    mma_f16(acc[mi][nj], af[mi], bf[nj]);
        }
    }

    #pragma unroll
    for (int mi = 0; mi < 2; mi++) {
        int r0 = m0 + wm * 32 + mi * 16 + (lane >> 2);
        #pragma unroll
        for (int nj = 0; nj < 8; nj++) {
            int cb = n0 + wn * 64 + nj * 8 + (lane & 3) * 2;
            float2 bv = *(const float2*)(bias + cb);
            #pragma unroll
            for (int half_ = 0; half_ < 2; half_++) {
                int r = r0 + half_ * 8;
                float vx = acc[mi][nj][half_ * 2 + 0] + bv.x;
                float vy = acc[mi][nj][half_ * 2 + 1] + bv.y;
                if (EPI == 1) {
                    __half2 rv = *(const __half2*)(res + (size_t)r * N + cb);
                    float2 rf = __half22float2(rv);
                    vx += rf.x; vy += rf.y;
                }
                if (EPI == 2) { vx = gelu_f(vx); vy = gelu_f(vy); }
                if (HOUT) {
                    *(__half2*)((__half*)Cout + (size_t)r * N + cb) = __floats2half2_rn(vx, vy);
                } else {
                    *(float2*)((float*)Cout + (size_t)r * N + cb) = make_float2(vx, vy);
                }
            }
        }
    }
    #undef ISSUE_STAGE
}

// ---------------- LayerNorm -> fp16 (input fp32 or fp16) ----------------
template<int INH>
__global__ void ln_kernel(const void* __restrict__ xin, const float* __restrict__ w,
                          const float* __restrict__ bb, __half* __restrict__ yh)
{
    int row = blockIdx.x;
    int t = threadIdx.x;
    float4 v;
    if (INH) {
        const __half2* xr = (const __half2*)((const __half*)xin + (size_t)row * Cv);
        float2 fa = __half22float2(xr[2 * t + 0]);
        float2 fb = __half22float2(xr[2 * t + 1]);
        v = make_float4(fa.x, fa.y, fb.x, fb.y);
    } else {
        v = ((const float4*)((const float*)xin + (size_t)row * Cv))[t];
    }
    float s  = v.x + v.y + v.z + v.w;
    float ss = v.x*v.x + v.y*v.y + v.z*v.z + v.w*v.w;
    #pragma unroll
    for (int o = 16; o > 0; o >>= 1) {
        s  += __shfl_xor_sync(0xffffffffu, s,  o);
        ss += __shfl_xor_sync(0xffffffffu, ss, o);
    }
    __shared__ float shs[8], shss[8], par[2];
    if ((t & 31) == 0) { shs[t >> 5] = s; shss[t >> 5] = ss; }
    __syncthreads();
    if (t == 0) {
        float S = 0.f, SS = 0.f;
        #pragma unroll
        for (int i = 0; i < 8; i++) { S += shs[i]; SS += shss[i]; }
        float mu  = S * (1.0f / 1024.0f);
        float var = SS * (1.0f / 1024.0f) - mu * mu;
        par[0] = mu; par[1] = rsqrtf(var + 1e-3f);
    }
    __syncthreads();
    float mu = par[0], rs = par[1];
    float4 wv = ((const float4*)w)[t];
    float4 bv = ((const float4*)bb)[t];
    float ox = (v.x - mu) * rs * wv.x + bv.x;
    float oy = (v.y - mu) * rs * wv.y + bv.y;
    float oz = (v.z - mu) * rs * wv.z + bv.z;
    float ow = (v.w - mu) * rs * wv.w + bv.w;
    __half2* yh2 = (__half2*)(yh + (size_t)row * Cv);
    yh2[2 * t + 0] = __floats2half2_rn(ox, oy);
    yh2[2 * t + 1] = __floats2half2_rn(oz, ow);
}

// ---------------- fused weight prep: pack QKV + transpose W1/W2 ----------------
#define PACK_BLKS 3072
#define W1T_BLKS  4096
#define W2T_BLKS  4096
__global__ void prep_kernel(const float* __restrict__ Wq, const float* __restrict__ Wk,
                            const float* __restrict__ Wv,
                            const float* __restrict__ bq, const float* __restrict__ bk,
                            const float* __restrict__ bv,
                            const float* __restrict__ W1, const float* __restrict__ W2,
                            __half* __restrict__ Wqkvh, float* __restrict__ bqkv,
                            __half* __restrict__ W1Th, __half* __restrict__ W2Th)
{
    __shared__ float tile[32][33];
    int blk = blockIdx.x, tid = threadIdx.x;
    if (blk < PACK_BLKS) {
        int gid = blk * 256 + tid;
        #pragma unroll
        for (int u = 0; u < 4; u++) {
            int idx = u * (PACK_BLKS * 256) + gid;
            int n = idx / Cv, k = idx % Cv;
            int sel = n >> 10;
            int hh = (n & 1023) >> 6, d = n & 63;
            const float* W = (sel == 0) ? Wq : (sel == 1) ? Wk : Wv;
            Wqkvh[idx] = __float2half(W[((size_t)hh * Cv + k) * DHv + d]);
            if (k == 0) {
                const float* B = (sel == 0) ? bq : (sel == 1) ? bk : bv;
                bqkv[n] = B[hh * DHv + d];
            }
        }
        return;
    }
    const float* in; __half* outp; int R, Cc, bx, by;
    if (blk < PACK_BLKS + W1T_BLKS) {
        int b2 = blk - PACK_BLKS;
        in = W1; outp = W1Th; R = Cv; Cc = Fv;
        bx = (b2 & 127) * 32; by = (b2 >> 7) * 32;
    } else {
        int b2 = blk - PACK_BLKS - W1T_BLKS;
        in = W2; outp = W2Th; R = Fv; Cc = Cv;
        bx = (b2 & 31) * 32; by = (b2 >> 5) * 32;
    }
    int tx = tid & 31, ty = tid >> 5;
    #pragma unroll
    for (int j = 0; j < 32; j += 8)
        tile[ty + j][tx] = in[(size_t)(by + ty + j) * Cc + bx + tx];
    __syncthreads();
    #pragma unroll
    for (int j = 0; j < 32; j += 8)
        outp[(size_t)(bx + ty + j) * R + by + tx] = __float2half(tile[tx][ty + j]);
}

// --------- ktv: Mpart[p] = (K[p]^T V[p]) * C^-0.5, 8-way T split, fp16 inputs ---------
__global__ void ktv_kernel(const __half* __restrict__ qkv, float* __restrict__ Mp)
{
    int bh = blockIdx.x;               // 128
    int part = blockIdx.y;             // 8
    int b = bh >> 4, h = bh & 15;
    __shared__ float Ks[32][64], Vs[32][64];
    int tid = threadIdx.x;
    int ty = tid >> 4, tx = tid & 15;
    float acc[4][4];
    #pragma unroll
    for (int i = 0; i < 4; i++)
        #pragma unroll
        for (int j = 0; j < 4; j++) acc[i][j] = 0.f;

    const __half* baseK = qkv + (size_t)b * Tv * QKVN + 1024 + h * 64;
    const __half* baseV = baseK + 1024;
    int tlo = part * (Tv / NPART);

    #pragma unroll
    for (int tile = 0; tile < Tv / NPART / 32; tile++) {
        int t0 = tlo + tile * 32;
        #pragma unroll
        for (int u = 0; u < 4; u++) {
            int idx = tid + 256 * u;
            int r = idx >> 5, c2 = idx & 31;
            __half2 kv = *(const __half2*)(baseK + (size_t)(t0 + r) * QKVN + c2 * 2);
            __half2 vv = *(const __half2*)(baseV + (size_t)(t0 + r) * QKVN + c2 * 2);
            float2 kf = __half22float2(kv), vf = __half22float2(vv);
            Ks[r][c2 * 2] = kf.x; Ks[r][c2 * 2 + 1] = kf.y;
            Vs[r][c2 * 2] = vf.x; Vs[r][c2 * 2 + 1] = vf.y;
        }
        __syncthreads();
        #pragma unroll
        for (int tt = 0; tt < 32; tt++) {
            float a[4], v[4];
            #pragma unroll
            for (int i = 0; i < 4; i++) a[i] = Ks[tt][ty * 4 + i];
            #pragma unroll
            for (int j = 0; j < 4; j++) v[j] = Vs[tt][tx * 4 + j];
            #pragma unroll
            for (int i = 0; i < 4; i++)
                #pragma unroll
                for (int j = 0; j < 4; j++)
                    acc[i][j] += a[i] * v[j];
        }
        __syncthreads();
    }
    float* out = Mp + ((size_t)part * 128 + bh) * 4096;
    #pragma unroll
    for (int i = 0; i < 4; i++)
        #pragma unroll
        for (int j = 0; j < 4; j++)
            out[(ty * 4 + i) * 64 + tx * 4 + j] = acc[i][j] * 0.03125f;
}

// --------- reduce Mpart -> M ---------
__global__ void mreduce_kernel(const float* __restrict__ Mp, float* __restrict__ M)
{
    int bh = blockIdx.x >> 2, q = blockIdx.x & 3;   // 512 blocks
    int base = q * 1024 + threadIdx.x;              // 256 thr, 4 elems each
    #pragma unroll
    for (int u = 0; u < 4; u++) {
        int i = base + 256 * u;
        float s = 0.f;
        #pragma unroll
        for (int p = 0; p < NPART; p++)
            s += Mp[((size_t)p * 128 + bh) * 4096 + i];
        M[(size_t)bh * 4096 + i] = s;
    }
}

// --------- W~p fold: Wt[b][n][h*64+d] = sum_e M_bh[d][e] * Wp[h*64+e][n] ---------
// grid (128, 16): one (b,h) x one 64-wide n chunk per block
__global__ void wtilde_kernel(const float* __restrict__ M, const float* __restrict__ Wp,
                              __half* __restrict__ Wt)
{
    int bh = blockIdx.x;
    int n0 = blockIdx.y * 64;
    int b = bh >> 4, h = bh & 15;
    __shared__ float Ms[64][65];
    __shared__ float Ws[64][65];
    int tid = threadIdx.x;

    const float* Mb = M + (size_t)bh * 4096;
    #pragma unroll
    for (int u = 0; u < 16; u++) {
        int i = tid + 256 * u;
        Ms[i >> 6][i & 63] = Mb[i];
    }
    #pragma unroll
    for (int u = 0; u < 16; u++) {
        int i = tid + 256 * u;
        int e = i >> 6, nl = i & 63;
        Ws[e][nl] = Wp[(size_t)(h * 64 + e) * Cv + n0 + nl];
    }
    __syncthreads();

    int d = tid & 63, ng = tid >> 6;
    float acc[16];
    #pragma unroll
    for (int v = 0; v < 16; v++) acc[v] = 0.f;
    #pragma unroll
    for (int e = 0; e < 64; e++) {
        float m = Ms[d][e];
        #pragma unroll
        for (int v = 0; v < 16; v++)
            acc[v] += m * Ws[e][ng * 16 + v];
    }
    __half* outb = Wt + (size_t)b * Cv * Cv + (size_t)(n0 + ng * 16) * Cv + h * 64 + d;
    #pragma unroll
    for (int v = 0; v < 16; v++)
        outb[(size_t)v * Cv] = __float2half(acc[v]);
}

// ---------------- launch ----------------
extern "C" void kernel_launch(void* const* d_in, const int* in_sizes, int n_in,
                              void* d_out, int out_size)
{
    (void)in_sizes; (void)n_in; (void)out_size;
    const float* x    = (const float*)d_in[0];
    const float* Wq   = (const float*)d_in[1];
    const float* bq   = (const float*)d_in[2];
    const float* Wk   = (const float*)d_in[3];
    const float* bk   = (const float*)d_in[4];
    const float* Wv   = (const float*)d_in[5];
    const float* bv   = (const float*)d_in[6];
    const float* Wp   = (const float*)d_in[7];
    const float* bp   = (const float*)d_in[8];
    const float* W1   = (const float*)d_in[9];
    const float* b1   = (const float*)d_in[10];
    const float* W2   = (const float*)d_in[11];
    const float* b2   = (const float*)d_in[12];
    const float* ln1w = (const float*)d_in[13];
    const float* ln1b = (const float*)d_in[14];
    const float* ln2w = (const float*)d_in[15];
    const float* ln2b = (const float*)d_in[16];
    float* out = (float*)d_out;

    float *pbqkv, *pMp, *pM;
    __half *px1h, *pqkvh, *pWqkvh, *pWt, *pyh, *px2h, *phh, *pW1Th, *pW2Th;
    cudaGetSymbolAddress((void**)&px1h,   g_x1h);
    cudaGetSymbolAddress((void**)&pqkvh,  g_qkvh);
    cudaGetSymbolAddress((void**)&pWqkvh, g_Wqkvh);
    cudaGetSymbolAddress((void**)&pbqkv,  g_bqkv);
    cudaGetSymbolAddress((void**)&pMp,    g_Mpart);
    cudaGetSymbolAddress((void**)&pM,     g_M);
    cudaGetSymbolAddress((void**)&pWt,    g_Wt);
    cudaGetSymbolAddress((void**)&pyh,    g_yh);
    cudaGetSymbolAddress((void**)&px2h,   g_x2h);
    cudaGetSymbolAddress((void**)&phh,    g_hh);
    cudaGetSymbolAddress((void**)&pW1Th,  g_W1Th);
    cudaGetSymbolAddress((void**)&pW2Th,  g_W2Th);

    const int smem = NSTAGE * STAGEB;   // 73728
    cudaFuncSetAttribute(mm_gemm<0,1,0>, cudaFuncAttributeMaxDynamicSharedMemorySize, smem);
    cudaFuncSetAttribute(mm_gemm<1,1,1>, cudaFuncAttributeMaxDynamicSharedMemorySize, smem);
    cudaFuncSetAttribute(mm_gemm<1,0,0>, cudaFuncAttributeMaxDynamicSharedMemorySize, smem);
    cudaFuncSetAttribute(mm_gemm<2,1,0>, cudaFuncAttributeMaxDynamicSharedMemorySize, smem);

    // fused weight prep (pack QKV + W1T + W2T)
    prep_kernel<<<PACK_BLKS + W1T_BLKS + W2T_BLKS, 256>>>(
        Wq, Wk, Wv, bq, bk, bv, W1, W2, pWqkvh, pbqkv, pW1Th, pW2Th);

    // x1 = LN1(x) -> fp16
    ln_kernel<0><<<BT, 256>>>(x, ln1w, ln1b, px1h);
    // qkv = x1 @ Wqkv^T + b -> fp16
    mm_gemm<0,1,0><<<dim3(QKVN/128, BT/128), 256, smem>>>(px1h, Cv, pWqkvh, pbqkv, nullptr, pqkvh, BT, QKVN, Cv);
    // M = (K^T V)/32 (8-way T split + reduce)
    ktv_kernel<<<dim3(Bv * Hv, NPART), 256>>>(pqkvh, pMp);
    mreduce_kernel<<<512, 256>>>(pMp, pM);
    // fold M into proj weights: Wt_b = blockdiag(M) @ Wp
    wtilde_kernel<<<dim3(Bv * Hv, Cv / 64), 256>>>(pM, Wp, pWt);
    // y = x1 + Q @ Wt_b + bp -> fp16  (A = Q section of qkv, lda=3C; B batched)
    mm_gemm<1,1,1><<<dim3(Cv/128, BT/128), 256, smem>>>(pqkvh, QKVN, pWt, bp, px1h, pyh, BT, Cv, Cv);
    // x2 = LN2(y) -> fp16
    ln_kernel<1><<<BT, 256>>>(pyh, ln2w, ln2b, px2h);
    // h = gelu(x2 @ W1 + b1) -> fp16
    mm_gemm<2,1,0><<<dim3(Fv/128, BT/128), 256, smem>>>(px2h, Cv, pW1Th, b1, nullptr, phh, BT, Fv, Cv);
    // out = x2 + h @ W2 + b2 -> fp32
    mm_gemm<1,0,0><<<dim3(Cv/128, BT/128), 256, smem>>>(phh, Fv, pW2Th, b2, px2h, out, BT, Cv, Fv);
}

// round 13
// speedup vs baseline: 1.0497x; 1.0262x over previous
#include <cuda_runtime.h>
#include <cuda_fp16.h>
#include <math.h>
#include <stdint.h>

// Problem constants
#define Bv 8
#define Tv 1024
#define Cv 1024
#define Hv 16
#define DHv 64
#define Fv 4096
#define BT (Bv*Tv)          // 8192
#define QKVN (3*Cv)         // 3072
#define KTV_NP 2

// ---------------- scratch ----------------
__device__ __half g_x1h[BT*Cv];         // ln1(x) fp16 (GEMM A + residual)
__device__ __half g_qkvh[BT*QKVN];      // qkv fp16
__device__ __half g_Wqkvh[QKVN*Cv];     // packed weight [N=3C, K=C] fp16
__device__ float  g_bqkv[QKVN];
__device__ float  g_Mpart[KTV_NP*128*DHv*DHv]; // partial (K^T V)/32
__device__ __half g_Wt[Bv*Cv*Cv];       // per-batch fused proj weight [b][n][k] fp16
__device__ __half g_yh[BT*Cv];          // x1 + attn fp16
__device__ __half g_x2h[BT*Cv];         // ln2(y) fp16
__device__ __half g_hh[BT*Fv];          // gelu(...) fp16
__device__ __half g_W1Th[Fv*Cv];        // [N=F, K=C] fp16
__device__ __half g_W2Th[Cv*Fv];        // [N=C, K=F] fp16

// ---------------- helpers ----------------
__device__ __forceinline__ uint32_t smem_u32(const void* p) {
    uint32_t a;
    asm("{ .reg .u64 t; cvta.to.shared.u64 t, %1; cvt.u32.u64 %0, t; }" : "=r"(a) : "l"(p));
    return a;
}
__device__ __forceinline__ void cp_async16(uint32_t dst, const void* src) {
    asm volatile("cp.async.cg.shared.global [%0], [%1], 16;" :: "r"(dst), "l"(src) : "memory");
}
__device__ __forceinline__ void cp_commit() { asm volatile("cp.async.commit_group;" ::: "memory"); }
template<int N> __device__ __forceinline__ void cp_wait() {
    asm volatile("cp.async.wait_group %0;" :: "n"(N) : "memory");
}
__device__ __forceinline__ void mma_f16(float* d, const uint32_t* a, const uint32_t* b) {
    asm volatile(
        "mma.sync.aligned.m16n8k16.row.col.f32.f16.f16.f32 "
        "{%0,%1,%2,%3}, {%4,%5,%6,%7}, {%8,%9}, {%0,%1,%2,%3};"
        : "+f"(d[0]), "+f"(d[1]), "+f"(d[2]), "+f"(d[3])
        : "r"(a[0]), "r"(a[1]), "r"(a[2]), "r"(a[3]), "r"(b[0]), "r"(b[1]));
}
__device__ __forceinline__ void ldsm_x4_t(uint32_t& r0, uint32_t& r1, uint32_t& r2, uint32_t& r3,
                                          uint32_t addr) {
    asm volatile("ldmatrix.sync.aligned.m8n8.x4.trans.shared.b16 {%0,%1,%2,%3}, [%4];"
        : "=r"(r0), "=r"(r1), "=r"(r2), "=r"(r3) : "r"(addr));
}
__device__ __forceinline__ float gelu_f(float v) {
    return 0.5f * v * (1.0f + erff(v * 0.70710678118654752f));
}

// ---------------- fp16 mma.sync GEMM (unchanged from R10) ----------------
#define NSTAGE 2
#define ROWH   72
#define TILEH  (128*ROWH)
#define TILEB  (TILEH*2)               // 18432 bytes
#define STAGEB (2*TILEB)               // 36864 bytes

template<int EPI, int HOUT, int BATB>
__global__ __launch_bounds__(256, 2)
void mm_gemm(const __half* __restrict__ A, int lda, const __half* __restrict__ B,
             const float* __restrict__ bias, const __half* __restrict__ res,
             void* __restrict__ Cout, int M, int N, int K)
{
    extern __shared__ __half sm[];
    const int tid = threadIdx.x, wid = tid >> 5, lane = tid & 31;
    const int m0 = blockIdx.y * 128, n0 = blockIdx.x * 128;
    const int wm = wid & 3, wn = wid >> 2;
    const uint32_t sbase = smem_u32(sm);
    const __half* Bb = BATB ? (B + (size_t)(m0 >> 10) * N * K) : B;

    const __half* aSrc[4]; uint32_t adst[4];
    const __half* bSrc[4]; uint32_t bdst[4];
    #pragma unroll
    for (int u = 0; u < 4; u++) {
        int idx = u * 256 + tid;
        int row = idx >> 3, c = idx & 7;
        aSrc[u] = A + (size_t)(m0 + row) * lda + c * 8;
        bSrc[u] = Bb + (size_t)(n0 + row) * K + c * 8;
        adst[u] = row * (ROWH * 2) + c * 16;
        bdst[u] = TILEB + adst[u];
    }

    #define ISSUE_STAGE(st, it) do {                                          \
        uint32_t _sb = sbase + (st) * STAGEB;                                 \
        _Pragma("unroll") for (int _u = 0; _u < 4; _u++)                      \
            cp_async16(_sb + adst[_u], aSrc[_u] + (size_t)(it) * 64);         \
        _Pragma("unroll") for (int _u = 0; _u < 4; _u++)                      \
            cp_async16(_sb + bdst[_u], bSrc[_u] + (size_t)(it) * 64);         \
        cp_commit(); } while (0)

    int aoff[2], boff[8];
    #pragma unroll
    for (int mi = 0; mi < 2; mi++)
        aoff[mi] = (wm * 32 + mi * 16 + (lane >> 2)) * ROWH + (lane & 3) * 2;
    #pragma unroll
    for (int nj = 0; nj < 8; nj++)
        boff[nj] = (wn * 64 + nj * 8 + (lane >> 2)) * ROWH + (lane & 3) * 2;

    float acc[2][8][4];
    #pragma unroll
    for (int mi = 0; mi < 2; mi++)
        #pragma unroll
        for (int nj = 0; nj < 8; nj++)
            #pragma unroll
            for (int q = 0; q < 4; q++) acc[mi][nj][q] = 0.f;

    const int NIT = K >> 6;
    ISSUE_STAGE(0, 0);

    for (int it = 0; it < NIT; it++) {
        cp_wait<0>();
        __syncthreads();
        if (it + 1 < NIT) ISSUE_STAGE((it + 1) & 1, it + 1);

        const __half* sA = sm + (it & 1) * (STAGEB / 2);
        const __half* sB = sA + TILEH;
        #pragma unroll
        for (int kk = 0; kk < 4; kk++) {
            uint32_t af[2][4], bf[8][2];
            #pragma unroll
            for (int mi = 0; mi < 2; mi++) {
                int o = aoff[mi] + kk * 16;
                af[mi][0] = *(const uint32_t*)(sA + o);
                af[mi][1] = *(const uint32_t*)(sA + o + 8 * ROWH);
                af[mi][2] = *(const uint32_t*)(sA + o + 8);
                af[mi][3] = *(const uint32_t*)(sA + o + 8 * ROWH + 8);
            }
            #pragma unroll
            for (int nj = 0; nj < 8; nj++) {
                int o = boff[nj] + kk * 16;
                bf[nj][0] = *(const uint32_t*)(sB + o);
                bf[nj][1] = *(const uint32_t*)(sB + o + 8);
            }
            #pragma unroll
            for (int mi = 0; mi < 2; mi++)
                #pragma unroll
                for (int nj = 0; nj < 8; nj++)
                    mma_f16(acc[mi][nj], af[mi], bf[nj]);
        }
    }

    #pragma unroll
    for (int mi = 0; mi < 2; mi++) {
        int r0 = m0 + wm * 32 + mi * 16 + (lane >> 2);
        #pragma unroll
        for (int nj = 0; nj < 8; nj++) {
            int cb = n0 + wn * 64 + nj * 8 + (lane & 3) * 2;
            float2 bv = *(const float2*)(bias + cb);
            #pragma unroll
            for (int half_ = 0; half_ < 2; half_++) {
                int r = r0 + half_ * 8;
                float vx = acc[mi][nj][half_ * 2 + 0] + bv.x;
                float vy = acc[mi][nj][half_ * 2 + 1] + bv.y;
                if (EPI == 1) {
                    __half2 rv = *(const __half2*)(res + (size_t)r * N + cb);
                    float2 rf = __half22float2(rv);
                    vx += rf.x; vy += rf.y;
                }
                if (EPI == 2) { vx = gelu_f(vx); vy = gelu_f(vy); }
                if (HOUT) {
                    *(__half2*)((__half*)Cout + (size_t)r * N + cb) = __floats2half2_rn(vx, vy);
                } else {
                    *(float2*)((float*)Cout + (size_t)r * N + cb) = make_float2(vx, vy);
                }
            }
        }
    }
    #undef ISSUE_STAGE
}

// ---------------- LayerNorm -> fp16 (input fp32 or fp16) ----------------
template<int INH>
__global__ void ln_kernel(const void* __restrict__ xin, const float* __restrict__ w,
                          const float* __restrict__ bb, __half* __restrict__ yh)
{
    int row = blockIdx.x;
    int t = threadIdx.x;
    float4 v;
    if (INH) {
        const __half2* xr = (const __half2*)((const __half*)xin + (size_t)row * Cv);
        float2 fa = __half22float2(xr[2 * t + 0]);
        float2 fb = __half22float2(xr[2 * t + 1]);
        v = make_float4(fa.x, fa.y, fb.x, fb.y);
    } else {
        v = ((const float4*)((const float*)xin + (size_t)row * Cv))[t];
    }
    float s  = v.x + v.y + v.z + v.w;
    float ss = v.x*v.x + v.y*v.y + v.z*v.z + v.w*v.w;
    #pragma unroll
    for (int o = 16; o > 0; o >>= 1) {
        s  += __shfl_xor_sync(0xffffffffu, s,  o);
        ss += __shfl_xor_sync(0xffffffffu, ss, o);
    }
    __shared__ float shs[8], shss[8], par[2];
    if ((t & 31) == 0) { shs[t >> 5] = s; shss[t >> 5] = ss; }
    __syncthreads();
    if (t == 0) {
        float S = 0.f, SS = 0.f;
        #pragma unroll
        for (int i = 0; i < 8; i++) { S += shs[i]; SS += shss[i]; }
        float mu  = S * (1.0f / 1024.0f);
        float var = SS * (1.0f / 1024.0f) - mu * mu;
        par[0] = mu; par[1] = rsqrtf(var + 1e-3f);
    }
    __syncthreads();
    float mu = par[0], rs = par[1];
    float4 wv = ((const float4*)w)[t];
    float4 bv = ((const float4*)bb)[t];
    float ox = (v.x - mu) * rs * wv.x + bv.x;
    float oy = (v.y - mu) * rs * wv.y + bv.y;
    float oz = (v.z - mu) * rs * wv.z + bv.z;
    float ow = (v.w - mu) * rs * wv.w + bv.w;
    __half2* yh2 = (__half2*)(yh + (size_t)row * Cv);
    yh2[2 * t + 0] = __floats2half2_rn(ox, oy);
    yh2[2 * t + 1] = __floats2half2_rn(oz, ow);
}

// ---------------- fused weight prep: pack QKV + transpose W1/W2 ----------------
#define PACK_BLKS 3072
#define W1T_BLKS  4096
#define W2T_BLKS  4096
__global__ void prep_kernel(const float* __restrict__ Wq, const float* __restrict__ Wk,
                            const float* __restrict__ Wv,
                            const float* __restrict__ bq, const float* __restrict__ bk,
                            const float* __restrict__ bv,
                            const float* __restrict__ W1, const float* __restrict__ W2,
                            __half* __restrict__ Wqkvh, float* __restrict__ bqkv,
                            __half* __restrict__ W1Th, __half* __restrict__ W2Th)
{
    __shared__ float tile[32][33];
    int blk = blockIdx.x, tid = threadIdx.x;
    if (blk < PACK_BLKS) {
        int gid = blk * 256 + tid;
        #pragma unroll
        for (int u = 0; u < 4; u++) {
            int idx = u * (PACK_BLKS * 256) + gid;
            int n = idx / Cv, k = idx % Cv;
            int sel = n >> 10;
            int hh = (n & 1023) >> 6, d = n & 63;
            const float* W = (sel == 0) ? Wq : (sel == 1) ? Wk : Wv;
            Wqkvh[idx] = __float2half(W[((size_t)hh * Cv + k) * DHv + d]);
            if (k == 0) {
                const float* B = (sel == 0) ? bq : (sel == 1) ? bk : bv;
                bqkv[n] = B[hh * DHv + d];
            }
        }
        return;
    }
    const float* in; __half* outp; int R, Cc, bx, by;
    if (blk < PACK_BLKS + W1T_BLKS) {
        int b2 = blk - PACK_BLKS;
        in = W1; outp = W1Th; R = Cv; Cc = Fv;
        bx = (b2 & 127) * 32; by = (b2 >> 7) * 32;
    } else {
        int b2 = blk - PACK_BLKS - W1T_BLKS;
        in = W2; outp = W2Th; R = Fv; Cc = Cv;
        bx = (b2 & 31) * 32; by = (b2 >> 5) * 32;
    }
    int tx = tid & 31, ty = tid >> 5;
    #pragma unroll
    for (int j = 0; j < 32; j += 8)
        tile[ty + j][tx] = in[(size_t)(by + ty + j) * Cc + bx + tx];
    __syncthreads();
    #pragma unroll
    for (int j = 0; j < 32; j += 8)
        outp[(size_t)(bx + ty + j) * R + by + tx] = __float2half(tile[tx][ty + j]);
}

// --------- ktv via mma: Mpart[p] = (K[p]^T V[p]) * C^-0.5 ---------
// grid (128, KTV_NP), 256 thr (8 warps 4(m)x2(n)); warp tile 16(d)x32(e).
// K,V chunks 64x64 fp16, rows padded to 72 halfs; A/B frags via ldmatrix.x4.trans.
#define KROW 72
__global__ __launch_bounds__(256, 2)
void ktv_kernel(const __half* __restrict__ qkv, float* __restrict__ Mp)
{
    __shared__ __half Ks[2][64 * KROW];
    __shared__ __half Vs[2][64 * KROW];
    int tid = threadIdx.x, wid = tid >> 5, lane = tid & 31;
    int bh = blockIdx.x, part = blockIdx.y;
    int b = bh >> 4, h = bh & 15;
    int wm = wid & 3, wn = wid >> 2;
    const __half* baseK = qkv + (size_t)b * Tv * QKVN + Cv + h * 64;
    const __half* baseV = baseK + Cv;
    int tlo = part * (Tv / KTV_NP);

    // cp.async slots: 64 rows x 8 chunks = 512 per tile; 2 K + 2 V per thread
    const __half* kSrc[2]; const __half* vSrc[2]; uint32_t dstOff[2];
    #pragma unroll
    for (int u = 0; u < 2; u++) {
        int idx = u * 256 + tid;
        int row = idx >> 3, c = idx & 7;
        kSrc[u] = baseK + (size_t)(tlo + row) * QKVN + c * 8;
        vSrc[u] = baseV + (size_t)(tlo + row) * QKVN + c * 8;
        dstOff[u] = (row * KROW + c * 8) * 2;
    }
    uint32_t ksb[2] = { smem_u32(Ks[0]), smem_u32(Ks[1]) };
    uint32_t vsb[2] = { smem_u32(Vs[0]), smem_u32(Vs[1]) };

    #define KTV_ISSUE(buf, ch) do {                                           \
        _Pragma("unroll") for (int _u = 0; _u < 2; _u++) {                    \
            cp_async16(ksb[buf] + dstOff[_u], kSrc[_u] + (size_t)(ch) * 64 * QKVN); \
            cp_async16(vsb[buf] + dstOff[_u], vSrc[_u] + (size_t)(ch) * 64 * QKVN); \
        }                                                                     \
        cp_commit(); } while (0)

    float acc[4][4];
    #pragma unroll
    for (int p = 0; p < 4; p++)
        #pragma unroll
        for (int q = 0; q < 4; q++) acc[p][q] = 0.f;

    const int NCH = (Tv / KTV_NP) / 64;     // 8
    int g = lane >> 3, r = lane & 7;
    // A: row = t0 + (g>>1)*8 + r, col = wm*16 + (g&1)*8
    uint32_t aoff = (((g >> 1) * 8 + r) * KROW + wm * 16 + (g & 1) * 8) * 2;
    // B: row = t0 + (g&1)*8 + r, col = n0 + (g>>1)*8   (n0 = wn*32 + p*16)
    uint32_t boff = (((g & 1) * 8 + r) * KROW + wn * 32 + (g >> 1) * 8) * 2;

    KTV_ISSUE(0, 0);
    for (int ch = 0; ch < NCH; ch++) {
        cp_wait<0>();
        __syncthreads();
        if (ch + 1 < NCH) KTV_ISSUE((ch + 1) & 1, ch + 1);
        int buf = ch & 1;
        #pragma unroll
        for (int ks = 0; ks < 4; ks++) {
            uint32_t trow = ks * 16 * KROW * 2;
            uint32_t a[4];
            ldsm_x4_t(a[0], a[1], a[2], a[3], ksb[buf] + trow + aoff);
            #pragma unroll
            for (int p = 0; p < 2; p++) {
                uint32_t bfr[4];
                ldsm_x4_t(bfr[0], bfr[1], bfr[2], bfr[3],
                          vsb[buf] + trow + boff + p * 16 * 2);
                mma_f16(acc[p * 2 + 0], a, bfr);
                mma_f16(acc[p * 2 + 1], a, bfr + 2);
            }
        }
        __syncthreads();
    }
    #undef KTV_ISSUE

    float* out = Mp + ((size_t)part * 128 + bh) * 4096;
    int row0 = wm * 16 + (lane >> 2);
    #pragma unroll
    for (int nt = 0; nt < 4; nt++) {
        int col = wn * 32 + nt * 8 + (lane & 3) * 2;
        out[row0 * 64 + col]           = acc[nt][0] * 0.03125f;
        out[row0 * 64 + col + 1]       = acc[nt][1] * 0.03125f;
        out[(row0 + 8) * 64 + col]     = acc[nt][2] * 0.03125f;
        out[(row0 + 8) * 64 + col + 1] = acc[nt][3] * 0.03125f;
    }
}

// --------- W~p fold: Wt[b][n][h*64+d] = sum_e M_bh[d][e] * Wp[h*64+e][n] ---------
// grid (128, 16); sums the KTV_NP M-partials during load.
__global__ void wtilde_kernel(const float* __restrict__ Mp, const float* __restrict__ Wp,
                              __half* __restrict__ Wt)
{
    int bh = blockIdx.x;
    int n0 = blockIdx.y * 64;
    int b = bh >> 4, h = bh & 15;
    __shared__ float Ms[64][65];
    __shared__ float Ws[64][65];
    int tid = threadIdx.x;

    const float* p0 = Mp + (size_t)bh * 4096;
    const float* p1 = Mp + ((size_t)128 + bh) * 4096;
    #pragma unroll
    for (int u = 0; u < 16; u++) {
        int i = tid + 256 * u;
        Ms[i >> 6][i & 63] = p0[i] + p1[i];
    }
    #pragma unroll
    for (int u = 0; u < 16; u++) {
        int i = tid + 256 * u;
        int e = i >> 6, nl = i & 63;
        Ws[e][nl] = Wp[(size_t)(h * 64 + e) * Cv + n0 + nl];
    }
    __syncthreads();

    int d = tid & 63, ng = tid >> 6;
    float acc[16];
    #pragma unroll
    for (int v = 0; v < 16; v++) acc[v] = 0.f;
    #pragma unroll
    for (int e = 0; e < 64; e++) {
        float m = Ms[d][e];
        #pragma unroll
        for (int v = 0; v < 16; v++)
            acc[v] += m * Ws[e][ng * 16 + v];
    }
    __half* outb = Wt + (size_t)b * Cv * Cv + (size_t)(n0 + ng * 16) * Cv + h * 64 + d;
    #pragma unroll
    for (int v = 0; v < 16; v++)
        outb[(size_t)v * Cv] = __float2half(acc[v]);
}

// ---------------- launch ----------------
extern "C" void kernel_launch(void* const* d_in, const int* in_sizes, int n_in,
                              void* d_out, int out_size)
{
    (void)in_sizes; (void)n_in; (void)out_size;
    const float* x    = (const float*)d_in[0];
    const float* Wq   = (const float*)d_in[1];
    const float* bq   = (const float*)d_in[2];
    const float* Wk   = (const float*)d_in[3];
    const float* bk   = (const float*)d_in[4];
    const float* Wv   = (const float*)d_in[5];
    const float* bv   = (const float*)d_in[6];
    const float* Wp   = (const float*)d_in[7];
    const float* bp   = (const float*)d_in[8];
    const float* W1   = (const float*)d_in[9];
    const float* b1   = (const float*)d_in[10];
    const float* W2   = (const float*)d_in[11];
    const float* b2   = (const float*)d_in[12];
    const float* ln1w = (const float*)d_in[13];
    const float* ln1b = (const float*)d_in[14];
    const float* ln2w = (const float*)d_in[15];
    const float* ln2b = (const float*)d_in[16];
    float* out = (float*)d_out;

    float *pbqkv, *pMp;
    __half *px1h, *pqkvh, *pWqkvh, *pWt, *pyh, *px2h, *phh, *pW1Th, *pW2Th;
    cudaGetSymbolAddress((void**)&px1h,   g_x1h);
    cudaGetSymbolAddress((void**)&pqkvh,  g_qkvh);
    cudaGetSymbolAddress((void**)&pWqkvh, g_Wqkvh);
    cudaGetSymbolAddress((void**)&pbqkv,  g_bqkv);
    cudaGetSymbolAddress((void**)&pMp,    g_Mpart);
    cudaGetSymbolAddress((void**)&pWt,    g_Wt);
    cudaGetSymbolAddress((void**)&pyh,    g_yh);
    cudaGetSymbolAddress((void**)&px2h,   g_x2h);
    cudaGetSymbolAddress((void**)&phh,    g_hh);
    cudaGetSymbolAddress((void**)&pW1Th,  g_W1Th);
    cudaGetSymbolAddress((void**)&pW2Th,  g_W2Th);

    const int smem = NSTAGE * STAGEB;   // 73728
    cudaFuncSetAttribute(mm_gemm<0,1,0>, cudaFuncAttributeMaxDynamicSharedMemorySize, smem);
    cudaFuncSetAttribute(mm_gemm<1,1,1>, cudaFuncAttributeMaxDynamicSharedMemorySize, smem);
    cudaFuncSetAttribute(mm_gemm<1,0,0>, cudaFuncAttributeMaxDynamicSharedMemorySize, smem);
    cudaFuncSetAttribute(mm_gemm<2,1,0>, cudaFuncAttributeMaxDynamicSharedMemorySize, smem);

    // fused weight prep (pack QKV + W1T + W2T)
    prep_kernel<<<PACK_BLKS + W1T_BLKS + W2T_BLKS, 256>>>(
        Wq, Wk, Wv, bq, bk, bv, W1, W2, pWqkvh, pbqkv, pW1Th, pW2Th);

    // x1 = LN1(x) -> fp16
    ln_kernel<0><<<BT, 256>>>(x, ln1w, ln1b, px1h);
    // qkv = x1 @ Wqkv^T + b -> fp16
    mm_gemm<0,1,0><<<dim3(QKVN/128, BT/128), 256, smem>>>(px1h, Cv, pWqkvh, pbqkv, nullptr, pqkvh, BT, QKVN, Cv);
    // M = (K^T V)/32 via mma (2-way T split; summed inside wtilde)
    ktv_kernel<<<dim3(Bv * Hv, KTV_NP), 256>>>(pqkvh, pMp);
    // fold M into proj weights: Wt_b = blockdiag(M) @ Wp
    wtilde_kernel<<<dim3(Bv * Hv, Cv / 64), 256>>>(pMp, Wp, pWt);
    // y = x1 + Q @ Wt_b + bp -> fp16
    mm_gemm<1,1,1><<<dim3(Cv/128, BT/128), 256, smem>>>(pqkvh, QKVN, pWt, bp, px1h, pyh, BT, Cv, Cv);
    // x2 = LN2(y) -> fp16
    ln_kernel<1><<<BT, 256>>>(pyh, ln2w, ln2b, px2h);
    // h = gelu(x2 @ W1 + b1) -> fp16
    mm_gemm<2,1,0><<<dim3(Fv/128, BT/128), 256, smem>>>(px2h, Cv, pW1Th, b1, nullptr, phh, BT, Fv, Cv);
    // out = x2 + h @ W2 + b2 -> fp32
    mm_gemm<1,0,0><<<dim3(Cv/128, BT/128), 256, smem>>>(phh, Fv, pW2Th, b2, px2h, out, BT, Cv, Fv);
}

// round 14
// speedup vs baseline: 1.0683x; 1.0178x over previous
#include <cuda_runtime.h>
#include <cuda_fp16.h>
#include <math.h>
#include <stdint.h>

// Problem constants
#define Bv 8
#define Tv 1024
#define Cv 1024
#define Hv 16
#define DHv 64
#define Fv 4096
#define BT (Bv*Tv)          // 8192
#define QKVN (3*Cv)         // 3072
#define KTV_NP 2

// ---------------- scratch ----------------
__device__ __half g_x1h[BT*Cv];         // ln1(x) fp16 (GEMM A + residual)
__device__ __half g_qkvh[BT*QKVN];      // qkv fp16
__device__ __half g_Wqkvh[QKVN*Cv];     // packed weight [N=3C, K=C] fp16
__device__ float  g_bqkv[QKVN];
__device__ float  g_Mpart[KTV_NP*128*DHv*DHv]; // partial (K^T V)/32
__device__ __half g_Wt[Bv*Cv*Cv];       // per-batch fused proj weight [b][n][k] fp16
__device__ __half g_yh[BT*Cv];          // x1 + attn fp16
__device__ __half g_x2h[BT*Cv];         // ln2(y) fp16
__device__ __half g_hh[BT*Fv];          // gelu(...) fp16
__device__ __half g_W1Th[Fv*Cv];        // [N=F, K=C] fp16
__device__ __half g_W2Th[Cv*Fv];        // [N=C, K=F] fp16

// ---------------- helpers ----------------
__device__ __forceinline__ uint32_t smem_u32(const void* p) {
    uint32_t a;
    asm("{ .reg .u64 t; cvta.to.shared.u64 t, %1; cvt.u32.u64 %0, t; }" : "=r"(a) : "l"(p));
    return a;
}
__device__ __forceinline__ void cp_async16(uint32_t dst, const void* src) {
    asm volatile("cp.async.cg.shared.global [%0], [%1], 16;" :: "r"(dst), "l"(src) : "memory");
}
__device__ __forceinline__ void cp_commit() { asm volatile("cp.async.commit_group;" ::: "memory"); }
template<int N> __device__ __forceinline__ void cp_wait() {
    asm volatile("cp.async.wait_group %0;" :: "n"(N) : "memory");
}
__device__ __forceinline__ void mma_f16(float* d, const uint32_t* a, const uint32_t* b) {
    asm volatile(
        "mma.sync.aligned.m16n8k16.row.col.f32.f16.f16.f32 "
        "{%0,%1,%2,%3}, {%4,%5,%6,%7}, {%8,%9}, {%0,%1,%2,%3};"
        : "+f"(d[0]), "+f"(d[1]), "+f"(d[2]), "+f"(d[3])
        : "r"(a[0]), "r"(a[1]), "r"(a[2]), "r"(a[3]), "r"(b[0]), "r"(b[1]));
}
__device__ __forceinline__ void ldsm_x4_t(uint32_t& r0, uint32_t& r1, uint32_t& r2, uint32_t& r3,
                                          uint32_t addr) {
    asm volatile("ldmatrix.sync.aligned.m8n8.x4.trans.shared.b16 {%0,%1,%2,%3}, [%4];"
        : "=r"(r0), "=r"(r1), "=r"(r2), "=r"(r3) : "r"(addr));
}
__device__ __forceinline__ float gelu_f(float v) {
    return 0.5f * v * (1.0f + erff(v * 0.70710678118654752f));
}

// ---------------- fp16 mma.sync GEMM (unchanged) ----------------
#define NSTAGE 2
#define ROWH   72
#define TILEH  (128*ROWH)
#define TILEB  (TILEH*2)               // 18432 bytes
#define STAGEB (2*TILEB)               // 36864 bytes

template<int EPI, int HOUT, int BATB>
__global__ __launch_bounds__(256, 2)
void mm_gemm(const __half* __restrict__ A, int lda, const __half* __restrict__ B,
             const float* __restrict__ bias, const __half* __restrict__ res,
             void* __restrict__ Cout, int M, int N, int K)
{
    extern __shared__ __half sm[];
    const int tid = threadIdx.x, wid = tid >> 5, lane = tid & 31;
    const int m0 = blockIdx.y * 128, n0 = blockIdx.x * 128;
    const int wm = wid & 3, wn = wid >> 2;
    const uint32_t sbase = smem_u32(sm);
    const __half* Bb = BATB ? (B + (size_t)(m0 >> 10) * N * K) : B;

    const __half* aSrc[4]; uint32_t adst[4];
    const __half* bSrc[4]; uint32_t bdst[4];
    #pragma unroll
    for (int u = 0; u < 4; u++) {
        int idx = u * 256 + tid;
        int row = idx >> 3, c = idx & 7;
        aSrc[u] = A + (size_t)(m0 + row) * lda + c * 8;
        bSrc[u] = Bb + (size_t)(n0 + row) * K + c * 8;
        adst[u] = row * (ROWH * 2) + c * 16;
        bdst[u] = TILEB + adst[u];
    }

    #define ISSUE_STAGE(st, it) do {                                          \
        uint32_t _sb = sbase + (st) * STAGEB;                                 \
        _Pragma("unroll") for (int _u = 0; _u < 4; _u++)                      \
            cp_async16(_sb + adst[_u], aSrc[_u] + (size_t)(it) * 64);         \
        _Pragma("unroll") for (int _u = 0; _u < 4; _u++)                      \
            cp_async16(_sb + bdst[_u], bSrc[_u] + (size_t)(it) * 64);         \
        cp_commit(); } while (0)

    int aoff[2], boff[8];
    #pragma unroll
    for (int mi = 0; mi < 2; mi++)
        aoff[mi] = (wm * 32 + mi * 16 + (lane >> 2)) * ROWH + (lane & 3) * 2;
    #pragma unroll
    for (int nj = 0; nj < 8; nj++)
        boff[nj] = (wn * 64 + nj * 8 + (lane >> 2)) * ROWH + (lane & 3) * 2;

    float acc[2][8][4];
    #pragma unroll
    for (int mi = 0; mi < 2; mi++)
        #pragma unroll
        for (int nj = 0; nj < 8; nj++)
            #pragma unroll
            for (int q = 0; q < 4; q++) acc[mi][nj][q] = 0.f;

    const int NIT = K >> 6;
    ISSUE_STAGE(0, 0);

    for (int it = 0; it < NIT; it++) {
        cp_wait<0>();
        __syncthreads();
        if (it + 1 < NIT) ISSUE_STAGE((it + 1) & 1, it + 1);

        const __half* sA = sm + (it & 1) * (STAGEB / 2);
        const __half* sB = sA + TILEH;
        #pragma unroll
        for (int kk = 0; kk < 4; kk++) {
            uint32_t af[2][4], bf[8][2];
            #pragma unroll
            for (int mi = 0; mi < 2; mi++) {
                int o = aoff[mi] + kk * 16;
                af[mi][0] = *(const uint32_t*)(sA + o);
                af[mi][1] = *(const uint32_t*)(sA + o + 8 * ROWH);
                af[mi][2] = *(const uint32_t*)(sA + o + 8);
                af[mi][3] = *(const uint32_t*)(sA + o + 8 * ROWH + 8);
            }
            #pragma unroll
            for (int nj = 0; nj < 8; nj++) {
                int o = boff[nj] + kk * 16;
                bf[nj][0] = *(const uint32_t*)(sB + o);
                bf[nj][1] = *(const uint32_t*)(sB + o + 8);
            }
            #pragma unroll
            for (int mi = 0; mi < 2; mi++)
                #pragma unroll
                for (int nj = 0; nj < 8; nj++)
                    mma_f16(acc[mi][nj], af[mi], bf[nj]);
        }
    }

    #pragma unroll
    for (int mi = 0; mi < 2; mi++) {
        int r0 = m0 + wm * 32 + mi * 16 + (lane >> 2);
        #pragma unroll
        for (int nj = 0; nj < 8; nj++) {
            int cb = n0 + wn * 64 + nj * 8 + (lane & 3) * 2;
            float2 bv = *(const float2*)(bias + cb);
            #pragma unroll
            for (int half_ = 0; half_ < 2; half_++) {
                int r = r0 + half_ * 8;
                float vx = acc[mi][nj][half_ * 2 + 0] + bv.x;
                float vy = acc[mi][nj][half_ * 2 + 1] + bv.y;
                if (EPI == 1) {
                    __half2 rv = *(const __half2*)(res + (size_t)r * N + cb);
                    float2 rf = __half22float2(rv);
                    vx += rf.x; vy += rf.y;
                }
                if (EPI == 2) { vx = gelu_f(vx); vy = gelu_f(vy); }
                if (HOUT) {
                    *(__half2*)((__half*)Cout + (size_t)r * N + cb) = __floats2half2_rn(vx, vy);
                } else {
                    *(float2*)((float*)Cout + (size_t)r * N + cb) = make_float2(vx, vy);
                }
            }
        }
    }
    #undef ISSUE_STAGE
}

// ---------------- LayerNorm core (device) ----------------
template<int INH>
__device__ __forceinline__ void ln_row(const void* __restrict__ xin,
                                       const float* __restrict__ w,
                                       const float* __restrict__ bb,
                                       __half* __restrict__ yh, int row, int t)
{
    float4 v;
    if (INH) {
        const __half2* xr = (const __half2*)((const __half*)xin + (size_t)row * Cv);
        float2 fa = __half22float2(xr[2 * t + 0]);
        float2 fb = __half22float2(xr[2 * t + 1]);
        v = make_float4(fa.x, fa.y, fb.x, fb.y);
    } else {
        v = ((const float4*)((const float*)xin + (size_t)row * Cv))[t];
    }
    float s  = v.x + v.y + v.z + v.w;
    float ss = v.x*v.x + v.y*v.y + v.z*v.z + v.w*v.w;
    #pragma unroll
    for (int o = 16; o > 0; o >>= 1) {
        s  += __shfl_xor_sync(0xffffffffu, s,  o);
        ss += __shfl_xor_sync(0xffffffffu, ss, o);
    }
    __shared__ float shs[8], shss[8], par[2];
    if ((t & 31) == 0) { shs[t >> 5] = s; shss[t >> 5] = ss; }
    __syncthreads();
    if (t == 0) {
        float S = 0.f, SS = 0.f;
        #pragma unroll
        for (int i = 0; i < 8; i++) { S += shs[i]; SS += shss[i]; }
        float mu  = S * (1.0f / 1024.0f);
        float var = SS * (1.0f / 1024.0f) - mu * mu;
        par[0] = mu; par[1] = rsqrtf(var + 1e-3f);
    }
    __syncthreads();
    float mu = par[0], rs = par[1];
    float4 wv = ((const float4*)w)[t];
    float4 bv = ((const float4*)bb)[t];
    float ox = (v.x - mu) * rs * wv.x + bv.x;
    float oy = (v.y - mu) * rs * wv.y + bv.y;
    float oz = (v.z - mu) * rs * wv.z + bv.z;
    float ow = (v.w - mu) * rs * wv.w + bv.w;
    __half2* yh2 = (__half2*)(yh + (size_t)row * Cv);
    yh2[2 * t + 0] = __floats2half2_rn(ox, oy);
    yh2[2 * t + 1] = __floats2half2_rn(oz, ow);
}

__global__ void ln_kernel(const __half* __restrict__ xin, const float* __restrict__ w,
                          const float* __restrict__ bb, __half* __restrict__ yh)
{
    ln_row<1>(xin, w, bb, yh, blockIdx.x, threadIdx.x);
}

// ---------------- fused LN1 + weight prep (one launch) ----------------
// grid: [0,8192) LN1 rows; then 3072 pack-transpose blocks (coalesced both sides);
// then 4096 W1T + 4096 W2T transpose blocks.
#define LN_BLKS   8192
#define PACK_BLKS 3072
#define W1T_BLKS  4096
#define W2T_BLKS  4096
__global__ void prep_kernel(const float* __restrict__ x,
                            const float* __restrict__ ln1w, const float* __restrict__ ln1b,
                            __half* __restrict__ x1h,
                            const float* __restrict__ Wq, const float* __restrict__ Wk,
                            const float* __restrict__ Wv,
                            const float* __restrict__ bq, const float* __restrict__ bk,
                            const float* __restrict__ bv,
                            const float* __restrict__ W1, const float* __restrict__ W2,
                            __half* __restrict__ Wqkvh, float* __restrict__ bqkv,
                            __half* __restrict__ W1Th, __half* __restrict__ W2Th)
{
    int blk = blockIdx.x, tid = threadIdx.x;
    if (blk < LN_BLKS) {
        ln_row<0>(x, ln1w, ln1b, x1h, blk, tid);
        return;
    }
    __shared__ float tile[32][33];
    int p = blk - LN_BLKS;
    int tx = tid & 31, ty = tid >> 5;              // 32x8
    if (p < PACK_BLKS) {
        // pack: per (sel,h) transpose 1024(k) x 64(d) -> Wqkvh[n=sel*1024+h*64+d][k]
        int sel = p >> 10;                          // 0..2
        int rem = p & 1023;
        int h = rem >> 6;                           // 0..15
        int t2 = rem & 63;                          // 64 tiles: kt 0..31, dt 0..1
        int k0 = (t2 >> 1) * 32, d0 = (t2 & 1) * 32;
        const float* W = (sel == 0) ? Wq : (sel == 1) ? Wk : Wv;
        const float* Wb = W + (size_t)h * Cv * DHv; // [k][d], d contiguous
        #pragma unroll
        for (int j = 0; j < 32; j += 8)
            tile[ty + j][tx] = Wb[(size_t)(k0 + ty + j) * DHv + d0 + tx];  // coalesced over d
        __syncthreads();
        int nbase = sel * 1024 + h * 64 + d0;
        #pragma unroll
        for (int j = 0; j < 32; j += 8)
            Wqkvh[(size_t)(nbase + ty + j) * Cv + k0 + tx] =               // coalesced over k
                __float2half(tile[tx][ty + j]);
        if (t2 == 0 && tid < 64) {
            const float* B = (sel == 0) ? bq : (sel == 1) ? bk : bv;
            bqkv[sel * 1024 + h * 64 + tid] = B[h * DHv + tid];
        }
        return;
    }
    const float* in; __half* outp; int R, Cc, bx, by;
    if (p < PACK_BLKS + W1T_BLKS) {
        int b2 = p - PACK_BLKS;
        in = W1; outp = W1Th; R = Cv; Cc = Fv;
        bx = (b2 & 127) * 32; by = (b2 >> 7) * 32;
    } else {
        int b2 = p - PACK_BLKS - W1T_BLKS;
        in = W2; outp = W2Th; R = Fv; Cc = Cv;
        bx = (b2 & 31) * 32; by = (b2 >> 5) * 32;
    }
    #pragma unroll
    for (int j = 0; j < 32; j += 8)
        tile[ty + j][tx] = in[(size_t)(by + ty + j) * Cc + bx + tx];
    __syncthreads();
    #pragma unroll
    for (int j = 0; j < 32; j += 8)
        outp[(size_t)(bx + ty + j) * R + by + tx] = __float2half(tile[tx][ty + j]);
}

// --------- ktv via mma: Mpart[p] = (K[p]^T V[p]) * C^-0.5 (unchanged) ---------
#define KROW 72
__global__ __launch_bounds__(256, 2)
void ktv_kernel(const __half* __restrict__ qkv, float* __restrict__ Mp)
{
    __shared__ __half Ks[2][64 * KROW];
    __shared__ __half Vs[2][64 * KROW];
    int tid = threadIdx.x, wid = tid >> 5, lane = tid & 31;
    int bh = blockIdx.x, part = blockIdx.y;
    int b = bh >> 4, h = bh & 15;
    int wm = wid & 3, wn = wid >> 2;
    const __half* baseK = qkv + (size_t)b * Tv * QKVN + Cv + h * 64;
    const __half* baseV = baseK + Cv;
    int tlo = part * (Tv / KTV_NP);

    const __half* kSrc[2]; const __half* vSrc[2]; uint32_t dstOff[2];
    #pragma unroll
    for (int u = 0; u < 2; u++) {
        int idx = u * 256 + tid;
        int row = idx >> 3, c = idx & 7;
        kSrc[u] = baseK + (size_t)(tlo + row) * QKVN + c * 8;
        vSrc[u] = baseV + (size_t)(tlo + row) * QKVN + c * 8;
        dstOff[u] = (row * KROW + c * 8) * 2;
    }
    uint32_t ksb[2] = { smem_u32(Ks[0]), smem_u32(Ks[1]) };
    uint32_t vsb[2] = { smem_u32(Vs[0]), smem_u32(Vs[1]) };

    #define KTV_ISSUE(buf, ch) do {                                           \
        _Pragma("unroll") for (int _u = 0; _u < 2; _u++) {                    \
            cp_async16(ksb[buf] + dstOff[_u], kSrc[_u] + (size_t)(ch) * 64 * QKVN); \
            cp_async16(vsb[buf] + dstOff[_u], vSrc[_u] + (size_t)(ch) * 64 * QKVN); \
        }                                                                     \
        cp_commit(); } while (0)

    float acc[4][4];
    #pragma unroll
    for (int p = 0; p < 4; p++)
        #pragma unroll
        for (int q = 0; q < 4; q++) acc[p][q] = 0.f;

    const int NCH = (Tv / KTV_NP) / 64;
    int g = lane >> 3, r = lane & 7;
    uint32_t aoff = (((g >> 1) * 8 + r) * KROW + wm * 16 + (g & 1) * 8) * 2;
    uint32_t boff = (((g & 1) * 8 + r) * KROW + wn * 32 + (g >> 1) * 8) * 2;

    KTV_ISSUE(0, 0);
    for (int ch = 0; ch < NCH; ch++) {
        cp_wait<0>();
        __syncthreads();
        if (ch + 1 < NCH) KTV_ISSUE((ch + 1) & 1, ch + 1);
        int buf = ch & 1;
        #pragma unroll
        for (int ks = 0; ks < 4; ks++) {
            uint32_t trow = ks * 16 * KROW * 2;
            uint32_t a[4];
            ldsm_x4_t(a[0], a[1], a[2], a[3], ksb[buf] + trow + aoff);
            #pragma unroll
            for (int p = 0; p < 2; p++) {
                uint32_t bfr[4];
                ldsm_x4_t(bfr[0], bfr[1], bfr[2], bfr[3],
                          vsb[buf] + trow + boff + p * 16 * 2);
                mma_f16(acc[p * 2 + 0], a, bfr);
                mma_f16(acc[p * 2 + 1], a, bfr + 2);
            }
        }
        __syncthreads();
    }
    #undef KTV_ISSUE

    float* out = Mp + ((size_t)part * 128 + bh) * 4096;
    int row0 = wm * 16 + (lane >> 2);
    #pragma unroll
    for (int nt = 0; nt < 4; nt++) {
        int col = wn * 32 + nt * 8 + (lane & 3) * 2;
        out[row0 * 64 + col]           = acc[nt][0] * 0.03125f;
        out[row0 * 64 + col + 1]       = acc[nt][1] * 0.03125f;
        out[(row0 + 8) * 64 + col]     = acc[nt][2] * 0.03125f;
        out[(row0 + 8) * 64 + col + 1] = acc[nt][3] * 0.03125f;
    }
}

// --------- W~p fold (unchanged) ---------
__global__ void wtilde_kernel(const float* __restrict__ Mp, const float* __restrict__ Wp,
                              __half* __restrict__ Wt)
{
    int bh = blockIdx.x;
    int n0 = blockIdx.y * 64;
    int b = bh >> 4, h = bh & 15;
    __shared__ float Ms[64][65];
    __shared__ float Ws[64][65];
    int tid = threadIdx.x;

    const float* p0 = Mp + (size_t)bh * 4096;
    const float* p1 = Mp + ((size_t)128 + bh) * 4096;
    #pragma unroll
    for (int u = 0; u < 16; u++) {
        int i = tid + 256 * u;
        Ms[i >> 6][i & 63] = p0[i] + p1[i];
    }
    #pragma unroll
    for (int u = 0; u < 16; u++) {
        int i = tid + 256 * u;
        int e = i >> 6, nl = i & 63;
        Ws[e][nl] = Wp[(size_t)(h * 64 + e) * Cv + n0 + nl];
    }
    __syncthreads();

    int d = tid & 63, ng = tid >> 6;
    float acc[16];
    #pragma unroll
    for (int v = 0; v < 16; v++) acc[v] = 0.f;
    #pragma unroll
    for (int e = 0; e < 64; e++) {
        float m = Ms[d][e];
        #pragma unroll
        for (int v = 0; v < 16; v++)
            acc[v] += m * Ws[e][ng * 16 + v];
    }
    __half* outb = Wt + (size_t)b * Cv * Cv + (size_t)(n0 + ng * 16) * Cv + h * 64 + d;
    #pragma unroll
    for (int v = 0; v < 16; v++)
        outb[(size_t)v * Cv] = __float2half(acc[v]);
}

// ---------------- launch ----------------
extern "C" void kernel_launch(void* const* d_in, const int* in_sizes, int n_in,
                              void* d_out, int out_size)
{
    (void)in_sizes; (void)n_in; (void)out_size;
    const float* x    = (const float*)d_in[0];
    const float* Wq   = (const float*)d_in[1];
    const float* bq   = (const float*)d_in[2];
    const float* Wk   = (const float*)d_in[3];
    const float* bk   = (const float*)d_in[4];
    const float* Wv   = (const float*)d_in[5];
    const float* bv   = (const float*)d_in[6];
    const float* Wp   = (const float*)d_in[7];
    const float* bp   = (const float*)d_in[8];
    const float* W1   = (const float*)d_in[9];
    const float* b1   = (const float*)d_in[10];
    const float* W2   = (const float*)d_in[11];
    const float* b2   = (const float*)d_in[12];
    const float* ln1w = (const float*)d_in[13];
    const float* ln1b = (const float*)d_in[14];
    const float* ln2w = (const float*)d_in[15];
    const float* ln2b = (const float*)d_in[16];
    float* out = (float*)d_out;

    float *pbqkv, *pMp;
    __half *px1h, *pqkvh, *pWqkvh, *pWt, *pyh, *px2h, *phh, *pW1Th, *pW2Th;
    cudaGetSymbolAddress((void**)&px1h,   g_x1h);
    cudaGetSymbolAddress((void**)&pqkvh,  g_qkvh);
    cudaGetSymbolAddress((void**)&pWqkvh, g_Wqkvh);
    cudaGetSymbolAddress((void**)&pbqkv,  g_bqkv);
    cudaGetSymbolAddress((void**)&pMp,    g_Mpart);
    cudaGetSymbolAddress((void**)&pWt,    g_Wt);
    cudaGetSymbolAddress((void**)&pyh,    g_yh);
    cudaGetSymbolAddress((void**)&px2h,   g_x2h);
    cudaGetSymbolAddress((void**)&phh,    g_hh);
    cudaGetSymbolAddress((void**)&pW1Th,  g_W1Th);
    cudaGetSymbolAddress((void**)&pW2Th,  g_W2Th);

    const int smem = NSTAGE * STAGEB;   // 73728
    cudaFuncSetAttribute(mm_gemm<0,1,0>, cudaFuncAttributeMaxDynamicSharedMemorySize, smem);
    cudaFuncSetAttribute(mm_gemm<1,1,1>, cudaFuncAttributeMaxDynamicSharedMemorySize, smem);
    cudaFuncSetAttribute(mm_gemm<1,0,0>, cudaFuncAttributeMaxDynamicSharedMemorySize, smem);
    cudaFuncSetAttribute(mm_gemm<2,1,0>, cudaFuncAttributeMaxDynamicSharedMemorySize, smem);

    // fused LN1 + weight prep (single launch)
    prep_kernel<<<LN_BLKS + PACK_BLKS + W1T_BLKS + W2T_BLKS, 256>>>(
        x, ln1w, ln1b, px1h,
        Wq, Wk, Wv, bq, bk, bv, W1, W2, pWqkvh, pbqkv, pW1Th, pW2Th);

    // qkv = x1 @ Wqkv^T + b -> fp16
    mm_gemm<0,1,0><<<dim3(QKVN/128, BT/128), 256, smem>>>(px1h, Cv, pWqkvh, pbqkv, nullptr, pqkvh, BT, QKVN, Cv);
    // M = (K^T V)/32 via mma (2-way T split; summed inside wtilde)
    ktv_kernel<<<dim3(Bv * Hv, KTV_NP), 256>>>(pqkvh, pMp);
    // fold M into proj weights: Wt_b = blockdiag(M) @ Wp
    wtilde_kernel<<<dim3(Bv * Hv, Cv / 64), 256>>>(pMp, Wp, pWt);
    // y = x1 + Q @ Wt_b + bp -> fp16
    mm_gemm<1,1,1><<<dim3(Cv/128, BT/128), 256, smem>>>(pqkvh, QKVN, pWt, bp, px1h, pyh, BT, Cv, Cv);
    // x2 = LN2(y) -> fp16
    ln_kernel<<<BT, 256>>>(pyh, ln2w, ln2b, px2h);
    // h = gelu(x2 @ W1 + b1) -> fp16
    mm_gemm<2,1,0><<<dim3(Fv/128, BT/128), 256, smem>>>(px2h, Cv, pW1Th, b1, nullptr, phh, BT, Fv, Cv);
    // out = x2 + h @ W2 + b2 -> fp32
    mm_gemm<1,0,0><<<dim3(Cv/128, BT/128), 256, smem>>>(phh, Fv, pW2Th, b2, px2h, out, BT, Cv, Fv);
}

// round 16
// speedup vs baseline: 1.1109x; 1.0398x over previous
#include <cuda_runtime.h>
#include <cuda_fp16.h>
#include <math.h>
#include <stdint.h>

// Problem constants
#define Bv 8
#define Tv 1024
#define Cv 1024
#define Hv 16
#define DHv 64
#define Fv 4096
#define BT (Bv*Tv)          // 8192
#define QKVN (3*Cv)         // 3072
#define KTV_NP 2

// ---------------- scratch ----------------
__device__ __half g_x1h[BT*Cv];         // ln1(x) fp16 (GEMM A + residual)
__device__ __half g_qkvh[BT*QKVN];      // qkv fp16
__device__ __half g_Wqkvh[QKVN*Cv];     // packed weight [N=3C, K=C] fp16
__device__ float  g_bqkv[QKVN];
__device__ float  g_Mpart[KTV_NP*128*DHv*DHv]; // partial (K^T V)/32
__device__ __half g_Wph[Cv*Cv];         // Wp fp16 [e][n]
__device__ __half g_Wt[Bv*Cv*Cv];       // per-batch fused proj weight [b][n][k] fp16
__device__ __half g_yh[BT*Cv];          // x1 + attn fp16
__device__ __half g_x2h[BT*Cv];         // ln2(y) fp16
__device__ __half g_hh[BT*Fv];          // gelu(...) fp16
__device__ __half g_W1Th[Fv*Cv];        // [N=F, K=C] fp16
__device__ __half g_W2Th[Cv*Fv];        // [N=C, K=F] fp16

// ---------------- helpers ----------------
__device__ __forceinline__ uint32_t smem_u32(const void* p) {
    uint32_t a;
    asm("{ .reg .u64 t; cvta.to.shared.u64 t, %1; cvt.u32.u64 %0, t; }" : "=r"(a) : "l"(p));
    return a;
}
__device__ __forceinline__ void cp_async16(uint32_t dst, const void* src) {
    asm volatile("cp.async.cg.shared.global [%0], [%1], 16;" :: "r"(dst), "l"(src) : "memory");
}
__device__ __forceinline__ void cp_commit() { asm volatile("cp.async.commit_group;" ::: "memory"); }
template<int N> __device__ __forceinline__ void cp_wait() {
    asm volatile("cp.async.wait_group %0;" :: "n"(N) : "memory");
}
__device__ __forceinline__ void mma_f16(float* d, const uint32_t* a, const uint32_t* b) {
    asm volatile(
        "mma.sync.aligned.m16n8k16.row.col.f32.f16.f16.f32 "
        "{%0,%1,%2,%3}, {%4,%5,%6,%7}, {%8,%9}, {%0,%1,%2,%3};"
        : "+f"(d[0]), "+f"(d[1]), "+f"(d[2]), "+f"(d[3])
        : "r"(a[0]), "r"(a[1]), "r"(a[2]), "r"(a[3]), "r"(b[0]), "r"(b[1]));
}
__device__ __forceinline__ void ldsm_x4_t(uint32_t& r0, uint32_t& r1, uint32_t& r2, uint32_t& r3,
                                          uint32_t addr) {
    asm volatile("ldmatrix.sync.aligned.m8n8.x4.trans.shared.b16 {%0,%1,%2,%3}, [%4];"
        : "=r"(r0), "=r"(r1), "=r"(r2), "=r"(r3) : "r"(addr));
}
__device__ __forceinline__ float gelu_f(float v) {
    return 0.5f * v * (1.0f + erff(v * 0.70710678118654752f));
}

// ---------------- fp16 mma.sync GEMM (unchanged) ----------------
#define NSTAGE 2
#define ROWH   72
#define TILEH  (128*ROWH)
#define TILEB  (TILEH*2)               // 18432 bytes
#define STAGEB (2*TILEB)               // 36864 bytes

template<int EPI, int HOUT, int BATB>
__global__ __launch_bounds__(256, 2)
void mm_gemm(const __half* __restrict__ A, int lda, const __half* __restrict__ B,
             const float* __restrict__ bias, const __half* __restrict__ res,
             void* __restrict__ Cout, int M, int N, int K)
{
    extern __shared__ __half sm[];
    const int tid = threadIdx.x, wid = tid >> 5, lane = tid & 31;
    const int m0 = blockIdx.y * 128, n0 = blockIdx.x * 128;
    const int wm = wid & 3, wn = wid >> 2;
    const uint32_t sbase = smem_u32(sm);
    const __half* Bb = BATB ? (B + (size_t)(m0 >> 10) * N * K) : B;

    const __half* aSrc[4]; uint32_t adst[4];
    const __half* bSrc[4]; uint32_t bdst[4];
    #pragma unroll
    for (int u = 0; u < 4; u++) {
        int idx = u * 256 + tid;
        int row = idx >> 3, c = idx & 7;
        aSrc[u] = A + (size_t)(m0 + row) * lda + c * 8;
        bSrc[u] = Bb + (size_t)(n0 + row) * K + c * 8;
        adst[u] = row * (ROWH * 2) + c * 16;
        bdst[u] = TILEB + adst[u];
    }

    #define ISSUE_STAGE(st, it) do {                                          \
        uint32_t _sb = sbase + (st) * STAGEB;                                 \
        _Pragma("unroll") for (int _u = 0; _u < 4; _u++)                      \
            cp_async16(_sb + adst[_u], aSrc[_u] + (size_t)(it) * 64);         \
        _Pragma("unroll") for (int _u = 0; _u < 4; _u++)                      \
            cp_async16(_sb + bdst[_u], bSrc[_u] + (size_t)(it) * 64);         \
        cp_commit(); } while (0)

    int aoff[2], boff[8];
    #pragma unroll
    for (int mi = 0; mi < 2; mi++)
        aoff[mi] = (wm * 32 + mi * 16 + (lane >> 2)) * ROWH + (lane & 3) * 2;
    #pragma unroll
    for (int nj = 0; nj < 8; nj++)
        boff[nj] = (wn * 64 + nj * 8 + (lane >> 2)) * ROWH + (lane & 3) * 2;

    float acc[2][8][4];
    #pragma unroll
    for (int mi = 0; mi < 2; mi++)
        #pragma unroll
        for (int nj = 0; nj < 8; nj++)
            #pragma unroll
            for (int q = 0; q < 4; q++) acc[mi][nj][q] = 0.f;

    const int NIT = K >> 6;
    ISSUE_STAGE(0, 0);

    for (int it = 0; it < NIT; it++) {
        cp_wait<0>();
        __syncthreads();
        if (it + 1 < NIT) ISSUE_STAGE((it + 1) & 1, it + 1);

        const __half* sA = sm + (it & 1) * (STAGEB / 2);
        const __half* sB = sA + TILEH;
        #pragma unroll
        for (int kk = 0; kk < 4; kk++) {
            uint32_t af[2][4], bf[8][2];
            #pragma unroll
            for (int mi = 0; mi < 2; mi++) {
                int o = aoff[mi] + kk * 16;
                af[mi][0] = *(const uint32_t*)(sA + o);
                af[mi][1] = *(const uint32_t*)(sA + o + 8 * ROWH);
                af[mi][2] = *(const uint32_t*)(sA + o + 8);
                af[mi][3] = *(const uint32_t*)(sA + o + 8 * ROWH + 8);
            }
            #pragma unroll
            for (int nj = 0; nj < 8; nj++) {
                int o = boff[nj] + kk * 16;
                bf[nj][0] = *(const uint32_t*)(sB + o);
                bf[nj][1] = *(const uint32_t*)(sB + o + 8);
            }
            #pragma unroll
            for (int mi = 0; mi < 2; mi++)
                #pragma unroll
                for (int nj = 0; nj < 8; nj++)
                    mma_f16(acc[mi][nj], af[mi], bf[nj]);
        }
    }

    #pragma unroll
    for (int mi = 0; mi < 2; mi++) {
        int r0 = m0 + wm * 32 + mi * 16 + (lane >> 2);
        #pragma unroll
        for (int nj = 0; nj < 8; nj++) {
            int cb = n0 + wn * 64 + nj * 8 + (lane & 3) * 2;
            float2 bv = *(const float2*)(bias + cb);
            #pragma unroll
            for (int half_ = 0; half_ < 2; half_++) {
                int r = r0 + half_ * 8;
                float vx = acc[mi][nj][half_ * 2 + 0] + bv.x;
                float vy = acc[mi][nj][half_ * 2 + 1] + bv.y;
                if (EPI == 1) {
                    __half2 rv = *(const __half2*)(res + (size_t)r * N + cb);
                    float2 rf = __half22float2(rv);
                    vx += rf.x; vy += rf.y;
                }
                if (EPI == 2) { vx = gelu_f(vx); vy = gelu_f(vy); }
                if (HOUT) {
                    *(__half2*)((__half*)Cout + (size_t)r * N + cb) = __floats2half2_rn(vx, vy);
                } else {
                    *(float2*)((float*)Cout + (size_t)r * N + cb) = make_float2(vx, vy);
                }
            }
        }
    }
    #undef ISSUE_STAGE
}

// ---------------- LayerNorm core (device) ----------------
template<int INH>
__device__ __forceinline__ void ln_row(const void* __restrict__ xin,
                                       const float* __restrict__ w,
                                       const float* __restrict__ bb,
                                       __half* __restrict__ yh, int row, int t)
{
    float4 v;
    if (INH) {
        const __half2* xr = (const __half2*)((const __half*)xin + (size_t)row * Cv);
        float2 fa = __half22float2(xr[2 * t + 0]);
        float2 fb = __half22float2(xr[2 * t + 1]);
        v = make_float4(fa.x, fa.y, fb.x, fb.y);
    } else {
        v = ((const float4*)((const float*)xin + (size_t)row * Cv))[t];
    }
    float s  = v.x + v.y + v.z + v.w;
    float ss = v.x*v.x + v.y*v.y + v.z*v.z + v.w*v.w;
    #pragma unroll
    for (int o = 16; o > 0; o >>= 1) {
        s  += __shfl_xor_sync(0xffffffffu, s,  o);
        ss += __shfl_xor_sync(0xffffffffu, ss, o);
    }
    __shared__ float shs[8], shss[8], par[2];
    if ((t & 31) == 0) { shs[t >> 5] = s; shss[t >> 5] = ss; }
    __syncthreads();
    if (t == 0) {
        float S = 0.f, SS = 0.f;
        #pragma unroll
        for (int i = 0; i < 8; i++) { S += shs[i]; SS += shss[i]; }
        float mu  = S * (1.0f / 1024.0f);
        float var = SS * (1.0f / 1024.0f) - mu * mu;
        par[0] = mu; par[1] = rsqrtf(var + 1e-3f);
    }
    __syncthreads();
    float mu = par[0], rs = par[1];
    float4 wv = ((const float4*)w)[t];
    float4 bv = ((const float4*)bb)[t];
    float ox = (v.x - mu) * rs * wv.x + bv.x;
    float oy = (v.y - mu) * rs * wv.y + bv.y;
    float oz = (v.z - mu) * rs * wv.z + bv.z;
    float ow = (v.w - mu) * rs * wv.w + bv.w;
    __half2* yh2 = (__half2*)(yh + (size_t)row * Cv);
    yh2[2 * t + 0] = __floats2half2_rn(ox, oy);
    yh2[2 * t + 1] = __floats2half2_rn(oz, ow);
}

__global__ void ln_kernel(const __half* __restrict__ xin, const float* __restrict__ w,
                          const float* __restrict__ bb, __half* __restrict__ yh)
{
    ln_row<1>(xin, w, bb, yh, blockIdx.x, threadIdx.x);
}

// ---------------- fused LN1 + weight prep (one launch) ----------------
#define LN_BLKS   8192
#define PACK_BLKS 3072
#define W1T_BLKS  4096
#define W2T_BLKS  4096
#define WPH_BLKS  1024
__global__ void prep_kernel(const float* __restrict__ x,
                            const float* __restrict__ ln1w, const float* __restrict__ ln1b,
                            __half* __restrict__ x1h,
                            const float* __restrict__ Wq, const float* __restrict__ Wk,
                            const float* __restrict__ Wv,
                            const float* __restrict__ bq, const float* __restrict__ bk,
                            const float* __restrict__ bv,
                            const float* __restrict__ W1, const float* __restrict__ W2,
                            const float* __restrict__ Wp,
                            __half* __restrict__ Wqkvh, float* __restrict__ bqkv,
                            __half* __restrict__ W1Th, __half* __restrict__ W2Th,
                            __half* __restrict__ Wph)
{
    int blk = blockIdx.x, tid = threadIdx.x;
    if (blk < LN_BLKS) {
        ln_row<0>(x, ln1w, ln1b, x1h, blk, tid);
        return;
    }
    int p = blk - LN_BLKS;
    if (p >= PACK_BLKS + W1T_BLKS + W2T_BLKS) {
        // Wp fp16 copy: one row per block
        int r = p - (PACK_BLKS + W1T_BLKS + W2T_BLKS);
        float4 v = ((const float4*)(Wp + (size_t)r * Cv))[tid];
        __half2 h0 = __floats2half2_rn(v.x, v.y);
        __half2 h1 = __floats2half2_rn(v.z, v.w);
        __half2* dst = (__half2*)(Wph + (size_t)r * Cv);
        dst[2 * tid + 0] = h0;
        dst[2 * tid + 1] = h1;
        return;
    }
    __shared__ float tile[32][33];
    int tx = tid & 31, ty = tid >> 5;              // 32x8
    if (p < PACK_BLKS) {
        // pack: per (sel,h) transpose 1024(k) x 64(d) -> Wqkvh[n=sel*1024+h*64+d][k]
        int sel = p >> 10;
        int rem = p & 1023;
        int h = rem >> 6;
        int t2 = rem & 63;
        int k0 = (t2 >> 1) * 32, d0 = (t2 & 1) * 32;
        const float* W = (sel == 0) ? Wq : (sel == 1) ? Wk : Wv;
        const float* Wb = W + (size_t)h * Cv * DHv;
        #pragma unroll
        for (int j = 0; j < 32; j += 8)
            tile[ty + j][tx] = Wb[(size_t)(k0 + ty + j) * DHv + d0 + tx];
        __syncthreads();
        int nbase = sel * 1024 + h * 64 + d0;
        #pragma unroll
        for (int j = 0; j < 32; j += 8)
            Wqkvh[(size_t)(nbase + ty + j) * Cv + k0 + tx] =
                __float2half(tile[tx][ty + j]);
        if (t2 == 0 && tid < 64) {
            const float* B = (sel == 0) ? bq : (sel == 1) ? bk : bv;
            bqkv[sel * 1024 + h * 64 + tid] = B[h * DHv + tid];
        }
        return;
    }
    const float* in; __half* outp; int R, Cc, bx, by;
    if (p < PACK_BLKS + W1T_BLKS) {
        int b2 = p - PACK_BLKS;
        in = W1; outp = W1Th; R = Cv; Cc = Fv;
        bx = (b2 & 127) * 32; by = (b2 >> 7) * 32;
    } else {
        int b2 = p - PACK_BLKS - W1T_BLKS;
        in = W2; outp = W2Th; R = Fv; Cc = Cv;
        bx = (b2 & 31) * 32; by = (b2 >> 5) * 32;
    }
    #pragma unroll
    for (int j = 0; j < 32; j += 8)
        tile[ty + j][tx] = in[(size_t)(by + ty + j) * Cc + bx + tx];
    __syncthreads();
    #pragma unroll
    for (int j = 0; j < 32; j += 8)
        outp[(size_t)(bx + ty + j) * R + by + tx] = __float2half(tile[tx][ty + j]);
}

// --------- ktv via mma: Mpart[p] = (K[p]^T V[p]) * C^-0.5 (unchanged) ---------
#define KROW 72
__global__ __launch_bounds__(256, 2)
void ktv_kernel(const __half* __restrict__ qkv, float* __restrict__ Mp)
{
    __shared__ __half Ks[2][64 * KROW];
    __shared__ __half Vs[2][64 * KROW];
    int tid = threadIdx.x, wid = tid >> 5, lane = tid & 31;
    int bh = blockIdx.x, part = blockIdx.y;
    int b = bh >> 4, h = bh & 15;
    int wm = wid & 3, wn = wid >> 2;
    const __half* baseK = qkv + (size_t)b * Tv * QKVN + Cv + h * 64;
    const __half* baseV = baseK + Cv;
    int tlo = part * (Tv / KTV_NP);

    const __half* kSrc[2]; const __half* vSrc[2]; uint32_t dstOff[2];
    #pragma unroll
    for (int u = 0; u < 2; u++) {
        int idx = u * 256 + tid;
        int row = idx >> 3, c = idx & 7;
        kSrc[u] = baseK + (size_t)(tlo + row) * QKVN + c * 8;
        vSrc[u] = baseV + (size_t)(tlo + row) * QKVN + c * 8;
        dstOff[u] = (row * KROW + c * 8) * 2;
    }
    uint32_t ksb[2] = { smem_u32(Ks[0]), smem_u32(Ks[1]) };
    uint32_t vsb[2] = { smem_u32(Vs[0]), smem_u32(Vs[1]) };

    #define KTV_ISSUE(buf, ch) do {                                           \
        _Pragma("unroll") for (int _u = 0; _u < 2; _u++) {                    \
            cp_async16(ksb[buf] + dstOff[_u], kSrc[_u] + (size_t)(ch) * 64 * QKVN); \
            cp_async16(vsb[buf] + dstOff[_u], vSrc[_u] + (size_t)(ch) * 64 * QKVN); \
        }                                                                     \
        cp_commit(); } while (0)

    float acc[4][4];
    #pragma unroll
    for (int p = 0; p < 4; p++)
        #pragma unroll
        for (int q = 0; q < 4; q++) acc[p][q] = 0.f;

    const int NCH = (Tv / KTV_NP) / 64;
    int g = lane >> 3, r = lane & 7;
    uint32_t aoff = (((g >> 1) * 8 + r) * KROW + wm * 16 + (g & 1) * 8) * 2;
    uint32_t boff = (((g & 1) * 8 + r) * KROW + wn * 32 + (g >> 1) * 8) * 2;

    KTV_ISSUE(0, 0);
    for (int ch = 0; ch < NCH; ch++) {
        cp_wait<0>();
        __syncthreads();
        if (ch + 1 < NCH) KTV_ISSUE((ch + 1) & 1, ch + 1);
        int buf = ch & 1;
        #pragma unroll
        for (int ks = 0; ks < 4; ks++) {
            uint32_t trow = ks * 16 * KROW * 2;
            uint32_t a[4];
            ldsm_x4_t(a[0], a[1], a[2], a[3], ksb[buf] + trow + aoff);
            #pragma unroll
            for (int p = 0; p < 2; p++) {
                uint32_t bfr[4];
                ldsm_x4_t(bfr[0], bfr[1], bfr[2], bfr[3],
                          vsb[buf] + trow + boff + p * 16 * 2);
                mma_f16(acc[p * 2 + 0], a, bfr);
                mma_f16(acc[p * 2 + 1], a, bfr + 2);
            }
        }
        __syncthreads();
    }
    #undef KTV_ISSUE

    float* out = Mp + ((size_t)part * 128 + bh) * 4096;
    int row0 = wm * 16 + (lane >> 2);
    #pragma unroll
    for (int nt = 0; nt < 4; nt++) {
        int col = wn * 32 + nt * 8 + (lane & 3) * 2;
        out[row0 * 64 + col]           = acc[nt][0] * 0.03125f;
        out[row0 * 64 + col + 1]       = acc[nt][1] * 0.03125f;
        out[(row0 + 8) * 64 + col]     = acc[nt][2] * 0.03125f;
        out[(row0 + 8) * 64 + col + 1] = acc[nt][3] * 0.03125f;
    }
}

// --------- W~p fold via mma (transposed): Wt[b][n][h*64+d] = sum_e Wp[h*64+e][n]*M[d][e] ---------
// grid (128 bh, 4 n-chunks of 256), 256 thr. A = Wp^T (trans ldsm from [e][n]),
// B = M [d][e] (direct LDS), acc rows = n, cols = d -> direct half2 stores.
#define WROW 264    // 256 + 8 halfs
#define MROW 72
__global__ __launch_bounds__(256, 2)
void wtilde_kernel(const float* __restrict__ Mp, const __half* __restrict__ Wph,
                   __half* __restrict__ Wt)
{
    __shared__ __half Ws[64 * WROW];   // [e][n] 33792 B
    __shared__ __half Ms[64 * MROW];   // [d][e]  9216 B
    int tid = threadIdx.x, wid = tid >> 5, lane = tid & 31;
    int bh = blockIdx.x, nc = blockIdx.y;
    int b = bh >> 4, h = bh & 15;
    int n0 = nc * 256;
    uint32_t wsb = smem_u32(Ws);

    // load Wp tile [64 e][256 n] fp16 via cp.async: 2048 chunks, 8/thread
    #pragma unroll
    for (int u = 0; u < 8; u++) {
        int idx = u * 256 + tid;
        int row = idx >> 5, c = idx & 31;
        cp_async16(wsb + (row * WROW + c * 8) * 2,
                   Wph + (size_t)(h * 64 + row) * Cv + n0 + c * 8);
    }
    cp_commit();

    // build M tile [64 d][64 e] fp16 from 2 fp32 partials: 2048 half2, 8/thread
    const float* p0 = Mp + (size_t)bh * 4096;
    const float* p1 = Mp + ((size_t)128 + bh) * 4096;
    #pragma unroll
    for (int u = 0; u < 8; u++) {
        int j = u * 256 + tid;             // 0..2047
        int d = j >> 5, ep = j & 31;       // d row, e half2-pair
        float2 a = *(const float2*)(p0 + d * 64 + ep * 2);
        float2 c = *(const float2*)(p1 + d * 64 + ep * 2);
        *(__half2*)(Ms + d * MROW + ep * 2) = __floats2half2_rn(a.x + c.x, a.y + c.y);
    }
    cp_wait<0>();
    __syncthreads();

    // warp tiling: m(n-dim)=256 -> 8 warps x 32 rows (2 m16); n(d-dim)=64 -> 8 n8 tiles
    int g = lane >> 3, r = lane & 7;
    float acc[2][8][4];
    #pragma unroll
    for (int mi = 0; mi < 2; mi++)
        #pragma unroll
        for (int nj = 0; nj < 8; nj++)
            #pragma unroll
            for (int q = 0; q < 4; q++) acc[mi][nj][q] = 0.f;

    #pragma unroll
    for (int ks = 0; ks < 4; ks++) {
        uint32_t trow = ks * 16 * WROW * 2;
        uint32_t af[2][4];
        #pragma unroll
        for (int mi = 0; mi < 2; mi++) {
            uint32_t acol = wid * 32 + mi * 16;
            uint32_t aadr = wsb + trow +
                ((((g >> 1) * 8 + r) * WROW + acol + (g & 1) * 8) * 2);
            ldsm_x4_t(af[mi][0], af[mi][1], af[mi][2], af[mi][3], aadr);
        }
        uint32_t bf[8][2];
        #pragma unroll
        for (int nj = 0; nj < 8; nj++) {
            int o = (nj * 8 + (lane >> 2)) * MROW + ks * 16 + (lane & 3) * 2;
            bf[nj][0] = *(const uint32_t*)(Ms + o);
            bf[nj][1] = *(const uint32_t*)(Ms + o + 8);
        }
        #pragma unroll
        for (int mi = 0; mi < 2; mi++)
            #pragma unroll
            for (int nj = 0; nj < 8; nj++)
                mma_f16(acc[mi][nj], af[mi], bf[nj]);
    }

    // store: row = n0 + wid*32 + mi*16 + lane>>2 (+8), col d = nj*8 + (lane&3)*2
    __half* base = Wt + (size_t)b * Cv * Cv + (size_t)h * 64;
    #pragma unroll
    for (int mi = 0; mi < 2; mi++) {
        int nrow = n0 + wid * 32 + mi * 16 + (lane >> 2);
        #pragma unroll
        for (int nj = 0; nj < 8; nj++) {
            int d = nj * 8 + (lane & 3) * 2;
            *(__half2*)(base + (size_t)nrow * Cv + d) =
                __floats2half2_rn(acc[mi][nj][0], acc[mi][nj][1]);
            *(__half2*)(base + (size_t)(nrow + 8) * Cv + d) =
                __floats2half2_rn(acc[mi][nj][2], acc[mi][nj][3]);
        }
    }
}

// ---------------- launch ----------------
extern "C" void kernel_launch(void* const* d_in, const int* in_sizes, int n_in,
                              void* d_out, int out_size)
{
    (void)in_sizes; (void)n_in; (void)out_size;
    const float* x    = (const float*)d_in[0];
    const float* Wq   = (const float*)d_in[1];
    const float* bq   = (const float*)d_in[2];
    const float* Wk   = (const float*)d_in[3];
    const float* bk   = (const float*)d_in[4];
    const float* Wv   = (const float*)d_in[5];
    const float* bv   = (const float*)d_in[6];
    const float* Wp   = (const float*)d_in[7];
    const float* bp   = (const float*)d_in[8];
    const float* W1   = (const float*)d_in[9];
    const float* b1   = (const float*)d_in[10];
    const float* W2   = (const float*)d_in[11];
    const float* b2   = (const float*)d_in[12];
    const float* ln1w = (const float*)d_in[13];
    const float* ln1b = (const float*)d_in[14];
    const float* ln2w = (const float*)d_in[15];
    const float* ln2b = (const float*)d_in[16];
    float* out = (float*)d_out;

    float *pbqkv, *pMp;
    __half *px1h, *pqkvh, *pWqkvh, *pWph, *pWt, *pyh, *px2h, *phh, *pW1Th, *pW2Th;
    cudaGetSymbolAddress((void**)&px1h,   g_x1h);
    cudaGetSymbolAddress((void**)&pqkvh,  g_qkvh);
    cudaGetSymbolAddress((void**)&pWqkvh, g_Wqkvh);
    cudaGetSymbolAddress((void**)&pbqkv,  g_bqkv);
    cudaGetSymbolAddress((void**)&pMp,    g_Mpart);
    cudaGetSymbolAddress((void**)&pWph,   g_Wph);
    cudaGetSymbolAddress((void**)&pWt,    g_Wt);
    cudaGetSymbolAddress((void**)&pyh,    g_yh);
    cudaGetSymbolAddress((void**)&px2h,   g_x2h);
    cudaGetSymbolAddress((void**)&phh,    g_hh);
    cudaGetSymbolAddress((void**)&pW1Th,  g_W1Th);
    cudaGetSymbolAddress((void**)&pW2Th,  g_W2Th);

    const int smem = NSTAGE * STAGEB;   // 73728
    cudaFuncSetAttribute(mm_gemm<0,1,0>, cudaFuncAttributeMaxDynamicSharedMemorySize, smem);
    cudaFuncSetAttribute(mm_gemm<1,1,1>, cudaFuncAttributeMaxDynamicSharedMemorySize, smem);
    cudaFuncSetAttribute(mm_gemm<1,0,0>, cudaFuncAttributeMaxDynamicSharedMemorySize, smem);
    cudaFuncSetAttribute(mm_gemm<2,1,0>, cudaFuncAttributeMaxDynamicSharedMemorySize, smem);

    // fused LN1 + weight prep (single launch)
    prep_kernel<<<LN_BLKS + PACK_BLKS + W1T_BLKS + W2T_BLKS + WPH_BLKS, 256>>>(
        x, ln1w, ln1b, px1h,
        Wq, Wk, Wv, bq, bk, bv, W1, W2, Wp, pWqkvh, pbqkv, pW1Th, pW2Th, pWph);

    // qkv = x1 @ Wqkv^T + b -> fp16
    mm_gemm<0,1,0><<<dim3(QKVN/128, BT/128), 256, smem>>>(px1h, Cv, pWqkvh, pbqkv, nullptr, pqkvh, BT, QKVN, Cv);
    // M = (K^T V)/32 via mma (2-way T split)
    ktv_kernel<<<dim3(Bv * Hv, KTV_NP), 256>>>(pqkvh, pMp);
    // fold M into proj weights via mma: Wt_b = (Wp^T blockdiag(M)^T)^T
    wtilde_kernel<<<dim3(Bv * Hv, 4), 256>>>(pMp, pWph, pWt);
    // y = x1 + Q @ Wt_b + bp -> fp16
    mm_gemm<1,1,1><<<dim3(Cv/128, BT/128), 256, smem>>>(pqkvh, QKVN, pWt, bp, px1h, pyh, BT, Cv, Cv);
    // x2 = LN2(y) -> fp16
    ln_kernel<<<BT, 256>>>(pyh, ln2w, ln2b, px2h);
    // h = gelu(x2 @ W1 + b1) -> fp16
    mm_gemm<2,1,0><<<dim3(Fv/128, BT/128), 256, smem>>>(px2h, Cv, pW1Th, b1, nullptr, phh, BT, Fv, Cv);
    // out = x2 + h @ W2 + b2 -> fp32
    mm_gemm<1,0,0><<<dim3(Cv/128, BT/128), 256, smem>>>(phh, Fv, pW2Th, b2, px2h, out, BT, Cv, Fv);
}